// round 1
// baseline (speedup 1.0000x reference)
#include <cuda_runtime.h>
#include <math.h>

// ---------------- problem constants ----------------
#define Bn   32
#define Ln   256
#define Dd   768
#define ATT  100
#define Hh   5
#define DK   20
#define NROW (Bn*Ln)            // 8192

// ---------------- scratch (device globals; no cudaMalloc allowed) ----------
// offsets (floats)
#define OFF_XLN   0ll
#define OFF_G     6291456ll
#define OFF_Q     7110656ll
#define OFF_K     7929856ll
#define OFF_GO    8749056ll
#define OFF_GO2   9568256ll
#define OFF_AX    10387456ll
#define OFF_ADJ   11206656ll    // 32*5*256*256
#define OFF_HS    21692416ll    // 32*256*256
#define OFF_ASPC  23789568ll    // 32*100
#define OFF_ASP   23792768ll    // 32*20
#define OFF_ASPSC 23793408ll    // 32*5*256
#define OFF_GW1   23834368ll    // 8192*5
#define OFF_GW2   23875328ll
#define SCRATCH_TOTAL 23916288ll

__device__ float d_scratch[SCRATCH_TOTAL];

// ---------------- layernorm (ddof=1, eps added to std) ----------------
__global__ void ln_kernel(const float* __restrict__ x,
                          const float* __restrict__ ga,
                          const float* __restrict__ gb,
                          float* __restrict__ out) {
    int row = blockIdx.x;
    const float* xr = x + (long long)row * Dd;
    __shared__ float red[256];
    int t = threadIdx.x;
    float s = 0.f;
    for (int i = t; i < Dd; i += 256) s += xr[i];
    red[t] = s; __syncthreads();
    for (int o = 128; o > 0; o >>= 1) { if (t < o) red[t] += red[t + o]; __syncthreads(); }
    float mean = red[0] / (float)Dd;
    __syncthreads();
    float v = 0.f;
    for (int i = t; i < Dd; i += 256) { float d = xr[i] - mean; v += d * d; }
    red[t] = v; __syncthreads();
    for (int o = 128; o > 0; o >>= 1) { if (t < o) red[t] += red[t + o]; __syncthreads(); }
    float stdv = sqrtf(red[0] / (float)(Dd - 1));
    float inv = 1.f / (stdv + 1e-6f);
    float* outr = out + (long long)row * Dd;
    for (int i = t; i < Dd; i += 256)
        outr[i] = ga[i] * (xr[i] - mean) * inv + gb[i];
}

// ---------------- generic tiled SGEMM: C = A[MxK] @ B[KxN] (+bias)(relu) ---
#define BM 64
#define BN 64
#define BK 16
__global__ void sgemm_kernel(const float* __restrict__ A,
                             const float* __restrict__ Bw,
                             const float* __restrict__ bias,
                             float* __restrict__ C,
                             int M, int N, int K,
                             long long sA, long long sB, long long sC,
                             int relu) {
    A  += (long long)blockIdx.z * sA;
    Bw += (long long)blockIdx.z * sB;
    C  += (long long)blockIdx.z * sC;
    __shared__ __align__(16) float As[BK][68];
    __shared__ __align__(16) float Bs[BK][68];
    int tid = threadIdx.x;
    int tx = tid & 15, ty = tid >> 4;
    int m0 = blockIdx.x * BM, n0 = blockIdx.y * BN;
    float acc[4][4] = {};
    for (int k0 = 0; k0 < K; k0 += BK) {
        #pragma unroll
        for (int i = tid; i < BM * BK; i += 256) {
            int r = i >> 4, c = i & 15;
            int gm = m0 + r, gk = k0 + c;
            As[c][r] = (gm < M && gk < K) ? A[(long long)gm * K + gk] : 0.f;
        }
        #pragma unroll
        for (int i = tid; i < BK * BN; i += 256) {
            int r = i >> 6, c = i & 63;
            int gk = k0 + r, gn = n0 + c;
            Bs[r][c] = (gk < K && gn < N) ? Bw[(long long)gk * N + gn] : 0.f;
        }
        __syncthreads();
        #pragma unroll
        for (int kk = 0; kk < BK; kk++) {
            float4 a4 = *reinterpret_cast<const float4*>(&As[kk][ty * 4]);
            float4 b4 = *reinterpret_cast<const float4*>(&Bs[kk][tx * 4]);
            float a[4] = {a4.x, a4.y, a4.z, a4.w};
            float b[4] = {b4.x, b4.y, b4.z, b4.w};
            #pragma unroll
            for (int i = 0; i < 4; i++)
                #pragma unroll
                for (int j = 0; j < 4; j++)
                    acc[i][j] += a[i] * b[j];
        }
        __syncthreads();
    }
    #pragma unroll
    for (int i = 0; i < 4; i++) {
        int gm = m0 + ty * 4 + i;
        if (gm >= M) continue;
        #pragma unroll
        for (int j = 0; j < 4; j++) {
            int gn = n0 + tx * 4 + j;
            if (gn >= N) continue;
            float v = acc[i][j];
            if (bias) v += bias[gn];
            if (relu) v = fmaxf(v, 0.f);
            C[(long long)gm * N + gn] = v;
        }
    }
}

// ---------------- aspect pooling + asp = aspect @ dense_w + b -------------
__global__ void aspect_kernel(const float* __restrict__ g,
                              const float* __restrict__ amask,
                              const float* __restrict__ dense_w,
                              const float* __restrict__ dense_b,
                              float* __restrict__ aspect,
                              float* __restrict__ asp) {
    int b = blockIdx.x;
    __shared__ float sm[Ln];
    __shared__ float sa[ATT];
    __shared__ float wn;
    int t = threadIdx.x; // 128
    for (int i = t; i < Ln; i += 128) sm[i] = amask[b * Ln + i];
    __syncthreads();
    if (t == 0) { float w = 0.f; for (int i = 0; i < Ln; i++) w += sm[i]; wn = w; }
    __syncthreads();
    float inv = 1.f / wn;
    for (int c = t; c < ATT; c += 128) {
        float s = 0.f;
        for (int i = 0; i < Ln; i++) s += g[((long long)b * Ln + i) * ATT + c] * sm[i];
        sa[c] = s * inv;
    }
    __syncthreads();
    if (t < ATT) aspect[b * ATT + t] = sa[t];
    if (t < DK) {
        float s = dense_b[t];
        for (int c = 0; c < ATT; c++) s += sa[c] * dense_w[c * DK + t];
        asp[b * DK + t] = s;
    }
}

// ---------------- asp_sc[b,h,j] = tanh(asp . k[b,h,j,:] + bias) ----------
__global__ void aspsc_kernel(const float* __restrict__ asp,
                             const float* __restrict__ k,
                             const float* __restrict__ bias_m,
                             float* __restrict__ aspsc) {
    int bh = blockIdx.x; int b = bh / Hh, h = bh % Hh;
    __shared__ float sasp[DK];
    int t = threadIdx.x; // 256 = j
    if (t < DK) sasp[t] = asp[b * DK + t];
    __syncthreads();
    const float* kr = k + ((long long)b * Ln + t) * ATT + h * DK;
    float s = 0.f;
    #pragma unroll
    for (int d = 0; d < DK; d++) s += sasp[d] * kr[d];
    aspsc[(long long)bh * Ln + t] = tanhf(s + bias_m[0]);
}

// ---------------- scores + mask + softmax -> adj --------------------------
// grid (L/8, H, B), 256 thr (8 warps, one row per warp)
__global__ void scores_softmax_kernel(const float* __restrict__ q,
                                      const float* __restrict__ k,
                                      const float* __restrict__ aspsc,
                                      const int*   __restrict__ src_mask,
                                      const float* __restrict__ short_mask,
                                      float* __restrict__ adj) {
    int it = blockIdx.x, h = blockIdx.y, b = blockIdx.z;
    __shared__ float kt[Ln][21];
    __shared__ float addv[Ln];
    __shared__ int   msk[Ln];
    __shared__ float qs[8][20];
    int t = threadIdx.x;
    for (int idx = t; idx < Ln * DK; idx += 256) {
        int j = idx / DK, d = idx % DK;
        kt[j][d] = k[((long long)b * Ln + j) * ATT + h * DK + d];
    }
    addv[t] = aspsc[((long long)(b * Hh + h)) * Ln + t];
    msk[t]  = src_mask[b * Ln + t];
    for (int idx = t; idx < 8 * DK; idx += 256) {
        int r = idx / DK, d = idx % DK;
        qs[r][d] = q[((long long)b * Ln + it * 8 + r) * ATT + h * DK + d];
    }
    __syncthreads();
    int w = t >> 5, lane = t & 31;
    int i = it * 8 + w;
    const float* srow = short_mask + ((long long)b * Ln + i) * Ln;
    float sc[8];
    #pragma unroll
    for (int jj = 0; jj < 8; jj++) sc[jj] = 0.f;
    #pragma unroll
    for (int d = 0; d < DK; d++) {
        float qd = qs[w][d];
        #pragma unroll
        for (int jj = 0; jj < 8; jj++)
            sc[jj] += qd * kt[lane + jj * 32][d];
    }
    const float rsd = 0.22360679774997896f; // 1/sqrt(20)
    float mx = -3.4e38f;
    #pragma unroll
    for (int jj = 0; jj < 8; jj++) {
        int j = lane + jj * 32;
        float v = sc[jj] * rsd + addv[j];
        if (msk[j] == 0) v = -1e9f;
        v += srow[j];
        sc[jj] = v;
        mx = fmaxf(mx, v);
    }
    #pragma unroll
    for (int o = 16; o > 0; o >>= 1) mx = fmaxf(mx, __shfl_xor_sync(0xffffffffu, mx, o));
    float sum = 0.f;
    #pragma unroll
    for (int jj = 0; jj < 8; jj++) { sc[jj] = expf(sc[jj] - mx); sum += sc[jj]; }
    #pragma unroll
    for (int o = 16; o > 0; o >>= 1) sum += __shfl_xor_sync(0xffffffffu, sum, o);
    float invs = 1.f / sum;
    float* arow = adj + (((long long)(b * Hh + h)) * Ln + i) * Ln;
    #pragma unroll
    for (int jj = 0; jj < 8; jj++) arow[lane + jj * 32] = sc[jj] * invs;
}

// ---------------- hsum[b,i,j] = (1/H) * sum_h adj[b,h,i,j] ----------------
__global__ void hsum_kernel(const float* __restrict__ adj, float* __restrict__ hs) {
    long long idx = (long long)blockIdx.x * 256 + threadIdx.x; // B*L*L
    long long b = idx >> 16;           // /65536
    long long ij = idx & 65535;
    float s = 0.f;
    #pragma unroll
    for (int h = 0; h < Hh; h++) s += adj[(b * Hh + h) * 65536ll + ij];
    hs[idx] = s * 0.2f;
}

// ---------------- goW1/goW2 = go @ W1/W2 (100x5 each) ---------------------
__global__ void goW12_kernel(const float* __restrict__ go,
                             const float* __restrict__ Wx_w,
                             float* __restrict__ gW1, float* __restrict__ gW2) {
    int row = blockIdx.x;
    __shared__ float gr[ATT];
    int t = threadIdx.x; // 128
    if (t < ATT) gr[t] = go[(long long)row * ATT + t];
    __syncthreads();
    if (t < 10) {
        int kk = t % 5;
        const float* W = Wx_w + (t < 5 ? 25 : 525);  // W1 rows 5..104, W2 rows 105..204
        float s = 0.f;
        for (int c = 0; c < ATT; c++) s += gr[c] * W[c * 5 + kk];
        (t < 5 ? gW1 : gW2)[(long long)row * 5 + kk] = s;
    }
}

// ---------------- edge update (in place on adj) ----------------------------
__global__ void edge_kernel(float* __restrict__ adj,
                            const float* __restrict__ gW1,
                            const float* __restrict__ gW2,
                            const float* __restrict__ Wx_w,
                            const float* __restrict__ Wx_b) {
    __shared__ float Wa[25], bb[5];
    int t = threadIdx.x;
    if (t < 25) Wa[t] = Wx_w[t];
    if (t < 5)  bb[t] = Wx_b[t];
    __syncthreads();
    long long idx = (long long)blockIdx.x * 256 + t; // B*L*L
    long long b = idx >> 16;
    long long ij = idx & 65535;
    long long i = ij >> 8, j = ij & 255;
    float a[5];
    #pragma unroll
    for (int h = 0; h < Hh; h++) a[h] = adj[(b * Hh + h) * 65536ll + ij];
    const float* g1 = gW1 + (b * Ln + j) * 5;
    const float* g2 = gW2 + (b * Ln + i) * 5;
    #pragma unroll
    for (int kk = 0; kk < Hh; kk++) {
        float v = bb[kk] + g1[kk] + g2[kk];
        #pragma unroll
        for (int h = 0; h < Hh; h++) v += a[h] * Wa[h * 5 + kk];
        adj[(b * Hh + kk) * 65536ll + ij] = v;
    }
}

// ---------------- final: aspect pool over relu(go2), then clf -------------
__global__ void final_kernel(const float* __restrict__ go,
                             const float* __restrict__ amask,
                             const float* __restrict__ clf_w,
                             const float* __restrict__ clf_b,
                             float* __restrict__ out) {
    int b = blockIdx.x;
    __shared__ float sm[Ln];
    __shared__ float o1[ATT];
    __shared__ float wn;
    int t = threadIdx.x; // 128
    for (int i = t; i < Ln; i += 128) sm[i] = amask[b * Ln + i];
    __syncthreads();
    if (t == 0) { float w = 0.f; for (int i = 0; i < Ln; i++) w += sm[i]; wn = w; }
    __syncthreads();
    float inv = 1.f / wn;
    for (int c = t; c < ATT; c += 128) {
        float s = 0.f;
        for (int i = 0; i < Ln; i++)
            s += fmaxf(go[((long long)b * Ln + i) * ATT + c], 0.f) * sm[i];
        o1[c] = s * inv;
    }
    __syncthreads();
    if (t < 3) {
        float s = clf_b[t];
        for (int c = 0; c < ATT; c++) s += o1[c] * clf_w[c * 3 + t];
        out[b * 3 + t] = s;
    }
}

// ---------------- launch --------------------------------------------------
extern "C" void kernel_launch(void* const* d_in, const int* in_sizes, int n_in,
                              void* d_out, int out_size) {
    const float* seq     = (const float*)d_in[0];
    const int*   srcm    = (const int*)  d_in[1];
    const float* amask   = (const float*)d_in[2];
    const float* shortm  = (const float*)d_in[3];
    const float* ln_a    = (const float*)d_in[4];
    const float* ln_b    = (const float*)d_in[5];
    const float* Wxx_w   = (const float*)d_in[6];
    const float* Wxx_b   = (const float*)d_in[7];
    const float* q_w     = (const float*)d_in[8];
    const float* q_b     = (const float*)d_in[9];
    const float* k_w     = (const float*)d_in[10];
    const float* k_b     = (const float*)d_in[11];
    const float* dense_w = (const float*)d_in[12];
    const float* dense_b = (const float*)d_in[13];
    const float* bias_m  = (const float*)d_in[14];
    const float* W_w     = (const float*)d_in[15];
    const float* W_b     = (const float*)d_in[16];
    const float* Wx_w    = (const float*)d_in[17];
    const float* Wx_b    = (const float*)d_in[18];
    const float* clf_w   = (const float*)d_in[19];
    const float* clf_b   = (const float*)d_in[20];
    float* out = (float*)d_out;

    float* S = nullptr;
    cudaGetSymbolAddress((void**)&S, d_scratch);
    float* xln   = S + OFF_XLN;
    float* g     = S + OFF_G;
    float* q     = S + OFF_Q;
    float* k     = S + OFF_K;
    float* go    = S + OFF_GO;
    float* go2   = S + OFF_GO2;
    float* Ax    = S + OFF_AX;
    float* adj   = S + OFF_ADJ;
    float* hs    = S + OFF_HS;
    float* aspct = S + OFF_ASPC;
    float* asp   = S + OFF_ASP;
    float* aspsc = S + OFF_ASPSC;
    float* gW1   = S + OFF_GW1;
    float* gW2   = S + OFF_GW2;

    // 1. layernorm
    ln_kernel<<<NROW, 256>>>(seq, ln_a, ln_b, xln);
    // 2. g = xln @ Wxx + b
    sgemm_kernel<<<dim3(NROW / BM, 2, 1), 256>>>(xln, Wxx_w, Wxx_b, g,
                                                 NROW, ATT, Dd, 0, 0, 0, 0);
    // 3/4. q,k projections
    sgemm_kernel<<<dim3(NROW / BM, 2, 1), 256>>>(g, q_w, q_b, q,
                                                 NROW, ATT, ATT, 0, 0, 0, 0);
    sgemm_kernel<<<dim3(NROW / BM, 2, 1), 256>>>(g, k_w, k_b, k,
                                                 NROW, ATT, ATT, 0, 0, 0, 0);
    // 5. aspect pool + asp
    aspect_kernel<<<Bn, 128>>>(g, amask, dense_w, dense_b, aspct, asp);
    // 6. aspect scores
    aspsc_kernel<<<Bn * Hh, 256>>>(asp, k, bias_m, aspsc);
    // 7. scores + softmax -> adj
    scores_softmax_kernel<<<dim3(Ln / 8, Hh, Bn), 256>>>(q, k, aspsc, srcm, shortm, adj);

    // ---- GCN layer 0 ----
    hsum_kernel<<<(Bn * Ln * Ln) / 256, 256>>>(adj, hs);
    sgemm_kernel<<<dim3(Ln / BM, 2, Bn), 256>>>(hs, g, nullptr, Ax,
                                                Ln, ATT, Ln,
                                                (long long)Ln * Ln, (long long)Ln * ATT, (long long)Ln * ATT, 0);
    sgemm_kernel<<<dim3(NROW / BM, 2, 1), 256>>>(Ax, W_w, W_b, go,
                                                 NROW, ATT, ATT, 0, 0, 0, 1);
    // edge update
    goW12_kernel<<<NROW, 128>>>(go, Wx_w, gW1, gW2);
    edge_kernel<<<(Bn * Ln * Ln) / 256, 256>>>(adj, gW1, gW2, Wx_w, Wx_b);

    // ---- GCN layer 1 ----
    hsum_kernel<<<(Bn * Ln * Ln) / 256, 256>>>(adj, hs);
    sgemm_kernel<<<dim3(Ln / BM, 2, Bn), 256>>>(hs, go, nullptr, Ax,
                                                Ln, ATT, Ln,
                                                (long long)Ln * Ln, (long long)Ln * ATT, (long long)Ln * ATT, 0);
    sgemm_kernel<<<dim3(NROW / BM, 2, 1), 256>>>(Ax, W_w, W_b, go2,
                                                 NROW, ATT, ATT, 0, 0, 0, 1);

    // final
    final_kernel<<<Bn, 128>>>(go2, amask, clf_w, clf_b, out);
}

// round 2
// speedup vs baseline: 1.7568x; 1.7568x over previous
#include <cuda_runtime.h>
#include <math.h>

// ---------------- problem constants ----------------
#define Bn   32
#define Ln   256
#define Dd   768
#define ATT  100
#define Hh   5
#define DK   20
#define NROW (Bn*Ln)            // 8192

// ---------------- scratch (device globals; no cudaMalloc allowed) ----------
#define OFF_XLN   0ll
#define OFF_G     6291456ll
#define OFF_Q     7110656ll
#define OFF_K     7929856ll
#define OFF_GO    8749056ll
#define OFF_GO2   9568256ll
#define OFF_AX    10387456ll
#define OFF_ADJ   11206656ll    // 32*5*256*256
#define OFF_HS    21692416ll    // 32*256*256
#define OFF_ASPC  23789568ll    // 32*100
#define OFF_ASP   23792768ll    // 32*20
#define OFF_ASPSC 23793408ll    // 32*5*256
#define OFF_GW1   23834368ll    // 8192*5
#define OFF_GW2   23875328ll
#define SCRATCH_TOTAL 23916288ll

__device__ __align__(16) float d_scratch[SCRATCH_TOTAL];

// ---------------- layernorm: one warp per row, one pass --------------------
__global__ void ln_kernel(const float* __restrict__ x,
                          const float* __restrict__ ga,
                          const float* __restrict__ gb,
                          float* __restrict__ out) {
    int warp = threadIdx.x >> 5, lane = threadIdx.x & 31;
    int row = blockIdx.x * 8 + warp;
    const float4* xr = reinterpret_cast<const float4*>(x + (long long)row * Dd);
    float4 v[6];
    float sum = 0.f, sq = 0.f;
    #pragma unroll
    for (int i = 0; i < 6; i++) {
        v[i] = xr[lane + i * 32];
        sum += v[i].x + v[i].y + v[i].z + v[i].w;
        sq  += v[i].x*v[i].x + v[i].y*v[i].y + v[i].z*v[i].z + v[i].w*v[i].w;
    }
    #pragma unroll
    for (int o = 16; o > 0; o >>= 1) {
        sum += __shfl_xor_sync(0xffffffffu, sum, o);
        sq  += __shfl_xor_sync(0xffffffffu, sq,  o);
    }
    float mean = sum * (1.f / (float)Dd);
    float var = (sq - (float)Dd * mean * mean) * (1.f / (float)(Dd - 1));
    float inv = 1.f / (sqrtf(var) + 1e-6f);
    const float4* gav = reinterpret_cast<const float4*>(ga);
    const float4* gbv = reinterpret_cast<const float4*>(gb);
    float4* outr = reinterpret_cast<float4*>(out + (long long)row * Dd);
    #pragma unroll
    for (int i = 0; i < 6; i++) {
        int idx = lane + i * 32;
        float4 a4 = gav[idx], b4 = gbv[idx], o4;
        o4.x = a4.x * (v[i].x - mean) * inv + b4.x;
        o4.y = a4.y * (v[i].y - mean) * inv + b4.y;
        o4.z = a4.z * (v[i].z - mean) * inv + b4.z;
        o4.w = a4.w * (v[i].w - mean) * inv + b4.w;
        outr[idx] = o4;
    }
}

// ---------------- double-buffered SGEMM: C = A[MxK] @ B[KxN] (+bias)(relu) -
// Requirements used: M%64==0, N%4==0, K%4==0.
// Dual mode (B1 != null): blockIdx.z selects {B0,bias0,C0} or {B1,bias1,C1}.
// Batched mode (B1 == null): blockIdx.z applies strides sA/sB/sC.
#define BM 64
#define BN 64
#define BK 16
__global__ __launch_bounds__(256, 4)
void sgemm_kernel(const float* __restrict__ A,
                  const float* __restrict__ B0, const float* __restrict__ bias0, float* __restrict__ C0,
                  const float* __restrict__ B1, const float* __restrict__ bias1, float* __restrict__ C1,
                  int M, int N, int K,
                  long long sA, long long sB, long long sC, int relu) {
    const float* Bw; const float* bias; float* C;
    if (B1 != nullptr) {
        if (blockIdx.z == 0) { Bw = B0; bias = bias0; C = C0; }
        else                 { Bw = B1; bias = bias1; C = C1; }
    } else {
        A += (long long)blockIdx.z * sA;
        Bw = B0 + (long long)blockIdx.z * sB;
        bias = bias0;
        C = C0 + (long long)blockIdx.z * sC;
    }

    __shared__ __align__(16) float As[2][BK][BM + 4];
    __shared__ __align__(16) float Bs[2][BK][BN + 4];

    int tid = threadIdx.x;
    int tx = tid & 15, ty = tid >> 4;
    int m0 = blockIdx.x * BM, n0 = blockIdx.y * BN;

    int ar = tid >> 2;            // 0..63 row within A tile
    int ac = (tid & 3) << 2;      // 0,4,8,12 k offset
    int br = tid >> 4;            // 0..15 k row within B tile
    int bc = (tid & 15) << 2;     // 0..60 col offset

    const float* Arow = A + (long long)(m0 + ar) * K;
    int bn = n0 + bc;
    bool bnok = (bn < N);

    float acc[4][4] = {};
    float4 aR, bR;
    const float4 z4 = make_float4(0.f, 0.f, 0.f, 0.f);

    int nt = (K + BK - 1) / BK;

    // prefetch tile 0
    {
        int ka = ac, kb = br;
        aR = (ka < K) ? *reinterpret_cast<const float4*>(Arow + ka) : z4;
        bR = (kb < K && bnok) ? *reinterpret_cast<const float4*>(Bw + (long long)kb * N + bn) : z4;
    }
    int s = 0;
    for (int t = 0; t < nt; t++) {
        As[s][ac + 0][ar] = aR.x;
        As[s][ac + 1][ar] = aR.y;
        As[s][ac + 2][ar] = aR.z;
        As[s][ac + 3][ar] = aR.w;
        *reinterpret_cast<float4*>(&Bs[s][br][bc]) = bR;
        __syncthreads();
        if (t + 1 < nt) {
            int ka = (t + 1) * BK + ac;
            int kb = (t + 1) * BK + br;
            aR = (ka < K) ? *reinterpret_cast<const float4*>(Arow + ka) : z4;
            bR = (kb < K && bnok) ? *reinterpret_cast<const float4*>(Bw + (long long)kb * N + bn) : z4;
        }
        #pragma unroll
        for (int kk = 0; kk < BK; kk++) {
            float4 a4 = *reinterpret_cast<const float4*>(&As[s][kk][ty * 4]);
            float4 b4 = *reinterpret_cast<const float4*>(&Bs[s][kk][tx * 4]);
            acc[0][0] += a4.x * b4.x; acc[0][1] += a4.x * b4.y; acc[0][2] += a4.x * b4.z; acc[0][3] += a4.x * b4.w;
            acc[1][0] += a4.y * b4.x; acc[1][1] += a4.y * b4.y; acc[1][2] += a4.y * b4.z; acc[1][3] += a4.y * b4.w;
            acc[2][0] += a4.z * b4.x; acc[2][1] += a4.z * b4.y; acc[2][2] += a4.z * b4.z; acc[2][3] += a4.z * b4.w;
            acc[3][0] += a4.w * b4.x; acc[3][1] += a4.w * b4.y; acc[3][2] += a4.w * b4.z; acc[3][3] += a4.w * b4.w;
        }
        s ^= 1;
        __syncthreads();
    }

    int gn0 = n0 + tx * 4;
    float bv[4] = {0.f, 0.f, 0.f, 0.f};
    if (bias) {
        #pragma unroll
        for (int j = 0; j < 4; j++) if (gn0 + j < N) bv[j] = bias[gn0 + j];
    }
    #pragma unroll
    for (int i = 0; i < 4; i++) {
        int gm = m0 + ty * 4 + i;   // M%64==0 -> always valid
        float* crow = C + (long long)gm * N;
        float v[4];
        #pragma unroll
        for (int j = 0; j < 4; j++) {
            v[j] = acc[i][j] + bv[j];
            if (relu) v[j] = fmaxf(v[j], 0.f);
        }
        if (gn0 + 3 < N) {
            float4 o4 = make_float4(v[0], v[1], v[2], v[3]);
            *reinterpret_cast<float4*>(crow + gn0) = o4;
        } else {
            #pragma unroll
            for (int j = 0; j < 4; j++) if (gn0 + j < N) crow[gn0 + j] = v[j];
        }
    }
}

// ---------------- aspect pooling + asp = aspect @ dense_w + b -------------
__global__ void aspect_kernel(const float* __restrict__ g,
                              const float* __restrict__ amask,
                              const float* __restrict__ dense_w,
                              const float* __restrict__ dense_b,
                              float* __restrict__ aspect,
                              float* __restrict__ asp) {
    int b = blockIdx.x;
    __shared__ float sm[Ln];
    __shared__ float sa[ATT];
    __shared__ float wn;
    int t = threadIdx.x; // 128
    for (int i = t; i < Ln; i += 128) sm[i] = amask[b * Ln + i];
    __syncthreads();
    if (t == 0) { float w = 0.f; for (int i = 0; i < Ln; i++) w += sm[i]; wn = w; }
    __syncthreads();
    float inv = 1.f / wn;
    for (int c = t; c < ATT; c += 128) {
        float s = 0.f;
        for (int i = 0; i < Ln; i++) s += g[((long long)b * Ln + i) * ATT + c] * sm[i];
        sa[c] = s * inv;
    }
    __syncthreads();
    if (t < ATT) aspect[b * ATT + t] = sa[t];
    if (t < DK) {
        float s = dense_b[t];
        for (int c = 0; c < ATT; c++) s += sa[c] * dense_w[c * DK + t];
        asp[b * DK + t] = s;
    }
}

// ---------------- asp_sc[b,h,j] = tanh(asp . k[b,h,j,:] + bias) ----------
__global__ void aspsc_kernel(const float* __restrict__ asp,
                             const float* __restrict__ k,
                             const float* __restrict__ bias_m,
                             float* __restrict__ aspsc) {
    int bh = blockIdx.x; int b = bh / Hh, h = bh % Hh;
    __shared__ float sasp[DK];
    int t = threadIdx.x; // 256 = j
    if (t < DK) sasp[t] = asp[b * DK + t];
    __syncthreads();
    const float* kr = k + ((long long)b * Ln + t) * ATT + h * DK;
    float s = 0.f;
    #pragma unroll
    for (int d = 0; d < DK; d++) s += sasp[d] * kr[d];
    aspsc[(long long)bh * Ln + t] = tanhf(s + bias_m[0]);
}

// ---------------- scores + mask + softmax -> adj --------------------------
__global__ void scores_softmax_kernel(const float* __restrict__ q,
                                      const float* __restrict__ k,
                                      const float* __restrict__ aspsc,
                                      const int*   __restrict__ src_mask,
                                      const float* __restrict__ short_mask,
                                      float* __restrict__ adj) {
    int it = blockIdx.x, h = blockIdx.y, b = blockIdx.z;
    __shared__ float kt[Ln][21];
    __shared__ float addv[Ln];
    __shared__ int   msk[Ln];
    __shared__ float qs[8][20];
    int t = threadIdx.x;
    for (int idx = t; idx < Ln * DK; idx += 256) {
        int j = idx / DK, d = idx % DK;
        kt[j][d] = k[((long long)b * Ln + j) * ATT + h * DK + d];
    }
    addv[t] = aspsc[((long long)(b * Hh + h)) * Ln + t];
    msk[t]  = src_mask[b * Ln + t];
    for (int idx = t; idx < 8 * DK; idx += 256) {
        int r = idx / DK, d = idx % DK;
        qs[r][d] = q[((long long)b * Ln + it * 8 + r) * ATT + h * DK + d];
    }
    __syncthreads();
    int w = t >> 5, lane = t & 31;
    int i = it * 8 + w;
    const float* srow = short_mask + ((long long)b * Ln + i) * Ln;
    float sc[8];
    #pragma unroll
    for (int jj = 0; jj < 8; jj++) sc[jj] = 0.f;
    #pragma unroll
    for (int d = 0; d < DK; d++) {
        float qd = qs[w][d];
        #pragma unroll
        for (int jj = 0; jj < 8; jj++)
            sc[jj] += qd * kt[lane + jj * 32][d];
    }
    const float rsd = 0.22360679774997896f; // 1/sqrt(20)
    float mx = -3.4e38f;
    #pragma unroll
    for (int jj = 0; jj < 8; jj++) {
        int j = lane + jj * 32;
        float v = sc[jj] * rsd + addv[j];
        if (msk[j] == 0) v = -1e9f;
        v += srow[j];
        sc[jj] = v;
        mx = fmaxf(mx, v);
    }
    #pragma unroll
    for (int o = 16; o > 0; o >>= 1) mx = fmaxf(mx, __shfl_xor_sync(0xffffffffu, mx, o));
    float sum = 0.f;
    #pragma unroll
    for (int jj = 0; jj < 8; jj++) { sc[jj] = expf(sc[jj] - mx); sum += sc[jj]; }
    #pragma unroll
    for (int o = 16; o > 0; o >>= 1) sum += __shfl_xor_sync(0xffffffffu, sum, o);
    float invs = 1.f / sum;
    float* arow = adj + (((long long)(b * Hh + h)) * Ln + i) * Ln;
    #pragma unroll
    for (int jj = 0; jj < 8; jj++) arow[lane + jj * 32] = sc[jj] * invs;
}

// ---------------- hsum[b,i,j] = (1/H) * sum_h adj[b,h,i,j] (float4) -------
__global__ void hsum_kernel(const float* __restrict__ adj, float* __restrict__ hs) {
    long long idx = (long long)blockIdx.x * 256 + threadIdx.x; // over B*L*L/4
    long long b = idx >> 14;
    long long r = idx & 16383;
    const float4* base = reinterpret_cast<const float4*>(adj) + b * 5 * 16384 + r;
    float4 s = base[0];
    #pragma unroll
    for (int h = 1; h < Hh; h++) {
        float4 v = base[(long long)h * 16384];
        s.x += v.x; s.y += v.y; s.z += v.z; s.w += v.w;
    }
    s.x *= 0.2f; s.y *= 0.2f; s.z *= 0.2f; s.w *= 0.2f;
    reinterpret_cast<float4*>(hs)[idx] = s;
}

// ---------------- goW1/goW2 = go @ W1/W2 — warp per row --------------------
__global__ void goW12_kernel(const float* __restrict__ go,
                             const float* __restrict__ Wx_w,
                             float* __restrict__ gW1, float* __restrict__ gW2) {
    __shared__ float sW[2][ATT][5];
    int tid = threadIdx.x;
    for (int i = tid; i < 500; i += 256) {
        sW[0][i / 5][i % 5] = Wx_w[25 + i];
        sW[1][i / 5][i % 5] = Wx_w[525 + i];
    }
    __syncthreads();
    int warp = tid >> 5, lane = tid & 31;
    int row = blockIdx.x * 8 + warp;
    float4 g4 = make_float4(0.f, 0.f, 0.f, 0.f);
    int c0 = lane * 4;
    if (lane < 25) g4 = *reinterpret_cast<const float4*>(go + (long long)row * ATT + c0);
    #pragma unroll
    for (int kk = 0; kk < 5; kk++) {
        float s1 = 0.f, s2 = 0.f;
        if (lane < 25) {
            s1 = g4.x * sW[0][c0][kk] + g4.y * sW[0][c0 + 1][kk]
               + g4.z * sW[0][c0 + 2][kk] + g4.w * sW[0][c0 + 3][kk];
            s2 = g4.x * sW[1][c0][kk] + g4.y * sW[1][c0 + 1][kk]
               + g4.z * sW[1][c0 + 2][kk] + g4.w * sW[1][c0 + 3][kk];
        }
        #pragma unroll
        for (int o = 16; o > 0; o >>= 1) {
            s1 += __shfl_xor_sync(0xffffffffu, s1, o);
            s2 += __shfl_xor_sync(0xffffffffu, s2, o);
        }
        if (lane == 0) {
            gW1[(long long)row * 5 + kk] = s1;
            gW2[(long long)row * 5 + kk] = s2;
        }
    }
}

// ---------------- fused edge update + h-sum: hs = 0.2*sum_k(edge_k) -------
// Reads OLD adj, never materializes new adj (layer1 only needs hs).
__global__ void edgehs_kernel(const float* __restrict__ adj,
                              const float* __restrict__ gW1,
                              const float* __restrict__ gW2,
                              const float* __restrict__ Wx_w,
                              const float* __restrict__ Wx_b,
                              float* __restrict__ hs) {
    __shared__ float Wa[25], bb[5];
    int t = threadIdx.x;
    if (t < 25) Wa[t] = Wx_w[t];
    if (t < 5)  bb[t] = Wx_b[t];
    __syncthreads();
    long long idx = (long long)blockIdx.x * 256 + t; // over B*L*L/4
    long long b = idx >> 14;
    long long ij4 = idx & 16383;
    const float4* ap = reinterpret_cast<const float4*>(adj) + b * 5 * 16384 + ij4;
    float aa[5][4];
    #pragma unroll
    for (int h = 0; h < Hh; h++) {
        float4 v = ap[(long long)h * 16384];
        aa[h][0] = v.x; aa[h][1] = v.y; aa[h][2] = v.z; aa[h][3] = v.w;
    }
    int i  = (int)(ij4 >> 6);
    int j0 = ((int)ij4 & 63) << 2;
    const float* g2 = gW2 + ((b << 8) + i) * 5;
    float g2r[5];
    #pragma unroll
    for (int kk = 0; kk < 5; kk++) g2r[kk] = g2[kk];
    float g1r[4][5];
    #pragma unroll
    for (int jj = 0; jj < 4; jj++) {
        const float* g1 = gW1 + ((b << 8) + j0 + jj) * 5;
        #pragma unroll
        for (int kk = 0; kk < 5; kk++) g1r[jj][kk] = g1[kk];
    }
    float outv[4] = {0.f, 0.f, 0.f, 0.f};
    #pragma unroll
    for (int kk = 0; kk < 5; kk++) {
        float base = bb[kk] + g2r[kk];
        #pragma unroll
        for (int jj = 0; jj < 4; jj++) {
            float v = base + g1r[jj][kk];
            #pragma unroll
            for (int h = 0; h < Hh; h++) v += aa[h][jj] * Wa[h * 5 + kk];
            outv[jj] += v;
        }
    }
    float4 o = make_float4(outv[0] * 0.2f, outv[1] * 0.2f, outv[2] * 0.2f, outv[3] * 0.2f);
    reinterpret_cast<float4*>(hs)[idx] = o;
}

// ---------------- final: aspect pool over relu(go2), then clf -------------
__global__ void final_kernel(const float* __restrict__ go,
                             const float* __restrict__ amask,
                             const float* __restrict__ clf_w,
                             const float* __restrict__ clf_b,
                             float* __restrict__ out) {
    int b = blockIdx.x;
    __shared__ float sm[Ln];
    __shared__ float o1[ATT];
    __shared__ float wn;
    int t = threadIdx.x; // 128
    for (int i = t; i < Ln; i += 128) sm[i] = amask[b * Ln + i];
    __syncthreads();
    if (t == 0) { float w = 0.f; for (int i = 0; i < Ln; i++) w += sm[i]; wn = w; }
    __syncthreads();
    float inv = 1.f / wn;
    for (int c = t; c < ATT; c += 128) {
        float s = 0.f;
        for (int i = 0; i < Ln; i++)
            s += fmaxf(go[((long long)b * Ln + i) * ATT + c], 0.f) * sm[i];
        o1[c] = s * inv;
    }
    __syncthreads();
    if (t < 3) {
        float s = clf_b[t];
        for (int c = 0; c < ATT; c++) s += o1[c] * clf_w[c * 3 + t];
        out[b * 3 + t] = s;
    }
}

// ---------------- launch --------------------------------------------------
extern "C" void kernel_launch(void* const* d_in, const int* in_sizes, int n_in,
                              void* d_out, int out_size) {
    const float* seq     = (const float*)d_in[0];
    const int*   srcm    = (const int*)  d_in[1];
    const float* amask   = (const float*)d_in[2];
    const float* shortm  = (const float*)d_in[3];
    const float* ln_a    = (const float*)d_in[4];
    const float* ln_b    = (const float*)d_in[5];
    const float* Wxx_w   = (const float*)d_in[6];
    const float* Wxx_b   = (const float*)d_in[7];
    const float* q_w     = (const float*)d_in[8];
    const float* q_b     = (const float*)d_in[9];
    const float* k_w     = (const float*)d_in[10];
    const float* k_b     = (const float*)d_in[11];
    const float* dense_w = (const float*)d_in[12];
    const float* dense_b = (const float*)d_in[13];
    const float* bias_m  = (const float*)d_in[14];
    const float* W_w     = (const float*)d_in[15];
    const float* W_b     = (const float*)d_in[16];
    const float* Wx_w    = (const float*)d_in[17];
    const float* Wx_b    = (const float*)d_in[18];
    const float* clf_w   = (const float*)d_in[19];
    const float* clf_b   = (const float*)d_in[20];
    float* out = (float*)d_out;

    float* S = nullptr;
    cudaGetSymbolAddress((void**)&S, d_scratch);
    float* xln   = S + OFF_XLN;
    float* g     = S + OFF_G;
    float* q     = S + OFF_Q;
    float* k     = S + OFF_K;
    float* go    = S + OFF_GO;
    float* go2   = S + OFF_GO2;
    float* Ax    = S + OFF_AX;
    float* adj   = S + OFF_ADJ;
    float* hs    = S + OFF_HS;
    float* aspct = S + OFF_ASPC;
    float* asp   = S + OFF_ASP;
    float* aspsc = S + OFF_ASPSC;
    float* gW1   = S + OFF_GW1;
    float* gW2   = S + OFF_GW2;

    // 1. layernorm (warp per row)
    ln_kernel<<<NROW / 8, 256>>>(seq, ln_a, ln_b, xln);
    // 2. g = xln @ Wxx + b
    sgemm_kernel<<<dim3(NROW / BM, 2, 1), 256>>>(xln, Wxx_w, Wxx_b, g,
                                                 nullptr, nullptr, nullptr,
                                                 NROW, ATT, Dd, 0, 0, 0, 0);
    // 3. q and k projections in ONE launch (z=0 -> q, z=1 -> k)
    sgemm_kernel<<<dim3(NROW / BM, 2, 2), 256>>>(g, q_w, q_b, q,
                                                 k_w, k_b, k,
                                                 NROW, ATT, ATT, 0, 0, 0, 0);
    // 4. aspect pool + asp
    aspect_kernel<<<Bn, 128>>>(g, amask, dense_w, dense_b, aspct, asp);
    // 5. aspect scores
    aspsc_kernel<<<Bn * Hh, 256>>>(asp, k, bias_m, aspsc);
    // 6. scores + softmax -> adj
    scores_softmax_kernel<<<dim3(Ln / 8, Hh, Bn), 256>>>(q, k, aspsc, srcm, shortm, adj);

    // ---- GCN layer 0 ----
    hsum_kernel<<<(Bn * Ln * Ln / 4) / 256, 256>>>(adj, hs);
    sgemm_kernel<<<dim3(Ln / BM, 2, Bn), 256>>>(hs, g, nullptr, Ax,
                                                nullptr, nullptr, nullptr,
                                                Ln, ATT, Ln,
                                                (long long)Ln * Ln, (long long)Ln * ATT, (long long)Ln * ATT, 0);
    sgemm_kernel<<<dim3(NROW / BM, 2, 1), 256>>>(Ax, W_w, W_b, go,
                                                 nullptr, nullptr, nullptr,
                                                 NROW, ATT, ATT, 0, 0, 0, 1);
    // edge update fused with next hsum: hs = 0.2 * sum_k edge_k (adj unchanged)
    goW12_kernel<<<NROW / 8, 256>>>(go, Wx_w, gW1, gW2);
    edgehs_kernel<<<(Bn * Ln * Ln / 4) / 256, 256>>>(adj, gW1, gW2, Wx_w, Wx_b, hs);

    // ---- GCN layer 1 ----
    sgemm_kernel<<<dim3(Ln / BM, 2, Bn), 256>>>(hs, go, nullptr, Ax,
                                                nullptr, nullptr, nullptr,
                                                Ln, ATT, Ln,
                                                (long long)Ln * Ln, (long long)Ln * ATT, (long long)Ln * ATT, 0);
    sgemm_kernel<<<dim3(NROW / BM, 2, 1), 256>>>(Ax, W_w, W_b, go2,
                                                 nullptr, nullptr, nullptr,
                                                 NROW, ATT, ATT, 0, 0, 0, 1);

    // final
    final_kernel<<<Bn, 128>>>(go2, amask, clf_w, clf_b, out);
}

// round 3
// speedup vs baseline: 1.7709x; 1.0080x over previous
#include <cuda_runtime.h>
#include <math.h>

// ---------------- problem constants ----------------
#define Bn   32
#define Ln   256
#define Dd   768
#define ATT  100
#define Hh   5
#define DK   20
#define NROW (Bn*Ln)            // 8192

// ---------------- scratch (device globals; no cudaMalloc allowed) ----------
#define OFF_XLN   0ll
#define OFF_G     6291456ll
#define OFF_Q     7110656ll
#define OFF_K     7929856ll
#define OFF_GO    8749056ll
#define OFF_GO2   9568256ll
#define OFF_AX    10387456ll
#define OFF_ADJ   11206656ll    // 32*5*256*256
#define OFF_HS    21692416ll    // 32*256*256
#define OFF_ASP   23792768ll    // 32*20
#define OFF_GW1   23834368ll    // 8192*5
#define OFF_GW2   23875328ll
#define SCRATCH_TOTAL 23916288ll

__device__ __align__(16) float d_scratch[SCRATCH_TOTAL];

// ---------------- layernorm: one warp per row, one pass --------------------
__global__ void ln_kernel(const float* __restrict__ x,
                          const float* __restrict__ ga,
                          const float* __restrict__ gb,
                          float* __restrict__ out) {
    int warp = threadIdx.x >> 5, lane = threadIdx.x & 31;
    int row = blockIdx.x * 8 + warp;
    const float4* xr = reinterpret_cast<const float4*>(x + (long long)row * Dd);
    float4 v[6];
    float sum = 0.f, sq = 0.f;
    #pragma unroll
    for (int i = 0; i < 6; i++) {
        v[i] = xr[lane + i * 32];
        sum += v[i].x + v[i].y + v[i].z + v[i].w;
        sq  += v[i].x*v[i].x + v[i].y*v[i].y + v[i].z*v[i].z + v[i].w*v[i].w;
    }
    #pragma unroll
    for (int o = 16; o > 0; o >>= 1) {
        sum += __shfl_xor_sync(0xffffffffu, sum, o);
        sq  += __shfl_xor_sync(0xffffffffu, sq,  o);
    }
    float mean = sum * (1.f / (float)Dd);
    float var = (sq - (float)Dd * mean * mean) * (1.f / (float)(Dd - 1));
    float inv = 1.f / (sqrtf(var) + 1e-6f);
    const float4* gav = reinterpret_cast<const float4*>(ga);
    const float4* gbv = reinterpret_cast<const float4*>(gb);
    float4* outr = reinterpret_cast<float4*>(out + (long long)row * Dd);
    #pragma unroll
    for (int i = 0; i < 6; i++) {
        int idx = lane + i * 32;
        float4 a4 = gav[idx], b4 = gbv[idx], o4;
        o4.x = a4.x * (v[i].x - mean) * inv + b4.x;
        o4.y = a4.y * (v[i].y - mean) * inv + b4.y;
        o4.z = a4.z * (v[i].z - mean) * inv + b4.z;
        o4.w = a4.w * (v[i].w - mean) * inv + b4.w;
        outr[idx] = o4;
    }
}

// ---------------- double-buffered SGEMM ------------------------------------
#define BM 64
#define BN 64
#define BK 16
__global__ __launch_bounds__(256, 4)
void sgemm_kernel(const float* __restrict__ A,
                  const float* __restrict__ B0, const float* __restrict__ bias0, float* __restrict__ C0,
                  const float* __restrict__ B1, const float* __restrict__ bias1, float* __restrict__ C1,
                  int M, int N, int K,
                  long long sA, long long sB, long long sC, int relu) {
    const float* Bw; const float* bias; float* C;
    if (B1 != nullptr) {
        if (blockIdx.z == 0) { Bw = B0; bias = bias0; C = C0; }
        else                 { Bw = B1; bias = bias1; C = C1; }
    } else {
        A += (long long)blockIdx.z * sA;
        Bw = B0 + (long long)blockIdx.z * sB;
        bias = bias0;
        C = C0 + (long long)blockIdx.z * sC;
    }

    __shared__ __align__(16) float As[2][BK][BM + 4];
    __shared__ __align__(16) float Bs[2][BK][BN + 4];

    int tid = threadIdx.x;
    int tx = tid & 15, ty = tid >> 4;
    int m0 = blockIdx.x * BM, n0 = blockIdx.y * BN;

    int ar = tid >> 2;
    int ac = (tid & 3) << 2;
    int br = tid >> 4;
    int bc = (tid & 15) << 2;

    const float* Arow = A + (long long)(m0 + ar) * K;
    int bn = n0 + bc;
    bool bnok = (bn < N);

    float acc[4][4] = {};
    float4 aR, bR;
    const float4 z4 = make_float4(0.f, 0.f, 0.f, 0.f);

    int nt = (K + BK - 1) / BK;
    {
        int ka = ac, kb = br;
        aR = (ka < K) ? *reinterpret_cast<const float4*>(Arow + ka) : z4;
        bR = (kb < K && bnok) ? *reinterpret_cast<const float4*>(Bw + (long long)kb * N + bn) : z4;
    }
    int s = 0;
    for (int t = 0; t < nt; t++) {
        As[s][ac + 0][ar] = aR.x;
        As[s][ac + 1][ar] = aR.y;
        As[s][ac + 2][ar] = aR.z;
        As[s][ac + 3][ar] = aR.w;
        *reinterpret_cast<float4*>(&Bs[s][br][bc]) = bR;
        __syncthreads();
        if (t + 1 < nt) {
            int ka = (t + 1) * BK + ac;
            int kb = (t + 1) * BK + br;
            aR = (ka < K) ? *reinterpret_cast<const float4*>(Arow + ka) : z4;
            bR = (kb < K && bnok) ? *reinterpret_cast<const float4*>(Bw + (long long)kb * N + bn) : z4;
        }
        #pragma unroll
        for (int kk = 0; kk < BK; kk++) {
            float4 a4 = *reinterpret_cast<const float4*>(&As[s][kk][ty * 4]);
            float4 b4 = *reinterpret_cast<const float4*>(&Bs[s][kk][tx * 4]);
            acc[0][0] += a4.x * b4.x; acc[0][1] += a4.x * b4.y; acc[0][2] += a4.x * b4.z; acc[0][3] += a4.x * b4.w;
            acc[1][0] += a4.y * b4.x; acc[1][1] += a4.y * b4.y; acc[1][2] += a4.y * b4.z; acc[1][3] += a4.y * b4.w;
            acc[2][0] += a4.z * b4.x; acc[2][1] += a4.z * b4.y; acc[2][2] += a4.z * b4.z; acc[2][3] += a4.z * b4.w;
            acc[3][0] += a4.w * b4.x; acc[3][1] += a4.w * b4.y; acc[3][2] += a4.w * b4.z; acc[3][3] += a4.w * b4.w;
        }
        s ^= 1;
        __syncthreads();
    }

    int gn0 = n0 + tx * 4;
    float bv[4] = {0.f, 0.f, 0.f, 0.f};
    if (bias) {
        #pragma unroll
        for (int j = 0; j < 4; j++) if (gn0 + j < N) bv[j] = bias[gn0 + j];
    }
    #pragma unroll
    for (int i = 0; i < 4; i++) {
        int gm = m0 + ty * 4 + i;
        float* crow = C + (long long)gm * N;
        float v[4];
        #pragma unroll
        for (int j = 0; j < 4; j++) {
            v[j] = acc[i][j] + bv[j];
            if (relu) v[j] = fmaxf(v[j], 0.f);
        }
        if (gn0 + 3 < N) {
            *reinterpret_cast<float4*>(crow + gn0) = make_float4(v[0], v[1], v[2], v[3]);
        } else {
            #pragma unroll
            for (int j = 0; j < 4; j++) if (gn0 + j < N) crow[gn0 + j] = v[j];
        }
    }
}

// ---------------- aspect pooling + asp (parallel, coalesced) --------------
// grid Bn, block 256 (8 warps). warp w handles rows i = w*32..w*32+31,
// lanes span columns (4 per lane, coalesced). smem reduce across warps.
__global__ void aspect_kernel(const float* __restrict__ g,
                              const float* __restrict__ amask,
                              const float* __restrict__ dense_w,
                              const float* __restrict__ dense_b,
                              float* __restrict__ asp) {
    int b = blockIdx.x;
    int t = threadIdx.x, w = t >> 5, lane = t & 31;
    __shared__ float part[8][104];
    __shared__ float sa[104];
    __shared__ float wred[8];

    float acc[4] = {0.f, 0.f, 0.f, 0.f};
    float wsum = 0.f;
    const float* gb_ = g + (long long)b * Ln * ATT;
    const float* mb = amask + b * Ln;
    for (int i = w * 32; i < w * 32 + 32; i++) {
        float m = mb[i];
        wsum += m;
        if (m != 0.f) {
            const float* gr = gb_ + (long long)i * ATT;
            #pragma unroll
            for (int c4 = 0; c4 < 4; c4++) {
                int c = lane + c4 * 32;
                if (c < ATT) acc[c4] += gr[c] * m;
            }
        }
    }
    #pragma unroll
    for (int c4 = 0; c4 < 4; c4++) {
        int c = lane + c4 * 32;
        if (c < ATT) part[w][c] = acc[c4];
    }
    // wsum currently counted 32x per warp(every lane added same m) -> take lane0's
    if (lane == 0) wred[w] = wsum;
    __syncthreads();
    if (t < ATT) {
        float s = 0.f;
        #pragma unroll
        for (int ww = 0; ww < 8; ww++) s += part[ww][t];
        sa[t] = s;
    }
    if (t == 0) {
        float s = 0.f;
        #pragma unroll
        for (int ww = 0; ww < 8; ww++) s += wred[ww];
        wred[0] = 1.f / s;
    }
    __syncthreads();
    float inv = wred[0];
    if (t < DK) {
        float s = dense_b[t];
        for (int c = 0; c < ATT; c++) s += sa[c] * inv * dense_w[c * DK + t];
        asp[b * DK + t] = s;
    }
}

// ---- fused: aspsc + scores + mask + softmax -> adj, and hs = mean_h adj ---
// grid (Ln/8, Bn), 256 thr (8 warps, one row i per warp), loop over heads.
__global__ __launch_bounds__(256, 4)
void scores_fused_kernel(const float* __restrict__ q,
                         const float* __restrict__ k,
                         const float* __restrict__ asp,
                         const float* __restrict__ bias_m,
                         const int*   __restrict__ src_mask,
                         const float* __restrict__ short_mask,
                         float* __restrict__ adj,
                         float* __restrict__ hs) {
    int it = blockIdx.x, b = blockIdx.y;
    __shared__ float kt[Ln][21];
    __shared__ float addv[Ln];
    __shared__ float qs[8][20];
    __shared__ float sasp[DK];
    __shared__ int   msk[Ln];
    int t = threadIdx.x, w = t >> 5, lane = t & 31;
    int i = it * 8 + w;

    if (t < DK) sasp[t] = asp[b * DK + t];
    msk[t] = src_mask[b * Ln + t];

    // short_mask row -> registers (read once, reused across 5 heads)
    const float* srow = short_mask + ((long long)b * Ln + i) * Ln;
    float smr[8];
    #pragma unroll
    for (int jj = 0; jj < 8; jj++) smr[jj] = srow[lane + jj * 32];

    float hsacc[8] = {0.f, 0.f, 0.f, 0.f, 0.f, 0.f, 0.f, 0.f};
    const float rsd = 0.22360679774997896f; // 1/sqrt(20)
    float biasv = bias_m[0];

    for (int h = 0; h < Hh; h++) {
        __syncthreads();
        // load K tile for this head: thread t -> row j=t (5x float4)
        {
            const float4* kr = reinterpret_cast<const float4*>(
                k + ((long long)b * Ln + t) * ATT + h * DK);
            #pragma unroll
            for (int f = 0; f < 5; f++) {
                float4 v = kr[f];
                kt[t][f * 4 + 0] = v.x;
                kt[t][f * 4 + 1] = v.y;
                kt[t][f * 4 + 2] = v.z;
                kt[t][f * 4 + 3] = v.w;
            }
        }
        if (t < 160) {
            int r = t / 20, d = t % 20;
            qs[r][d] = q[((long long)b * Ln + it * 8 + r) * ATT + h * DK + d];
        }
        __syncthreads();
        // addv[j] = tanh(asp . k_j + bias)
        {
            float s = 0.f;
            #pragma unroll
            for (int d = 0; d < DK; d++) s += sasp[d] * kt[t][d];
            addv[t] = tanhf(s + biasv);
        }
        __syncthreads();

        float sc[8] = {0.f, 0.f, 0.f, 0.f, 0.f, 0.f, 0.f, 0.f};
        #pragma unroll
        for (int d = 0; d < DK; d++) {
            float qd = qs[w][d];
            #pragma unroll
            for (int jj = 0; jj < 8; jj++)
                sc[jj] += qd * kt[lane + jj * 32][d];
        }
        float mx = -3.4e38f;
        #pragma unroll
        for (int jj = 0; jj < 8; jj++) {
            int j = lane + jj * 32;
            float v = sc[jj] * rsd + addv[j];
            if (msk[j] == 0) v = -1e9f;
            v += smr[jj];
            sc[jj] = v;
            mx = fmaxf(mx, v);
        }
        #pragma unroll
        for (int o = 16; o > 0; o >>= 1) mx = fmaxf(mx, __shfl_xor_sync(0xffffffffu, mx, o));
        float sum = 0.f;
        #pragma unroll
        for (int jj = 0; jj < 8; jj++) { sc[jj] = expf(sc[jj] - mx); sum += sc[jj]; }
        #pragma unroll
        for (int o = 16; o > 0; o >>= 1) sum += __shfl_xor_sync(0xffffffffu, sum, o);
        float invs = 1.f / sum;
        float* arow = adj + (((long long)(b * Hh + h)) * Ln + i) * Ln;
        #pragma unroll
        for (int jj = 0; jj < 8; jj++) {
            float a = sc[jj] * invs;
            arow[lane + jj * 32] = a;
            hsacc[jj] += a;
        }
    }
    float* hrow = hs + ((long long)b * Ln + i) * Ln;
    #pragma unroll
    for (int jj = 0; jj < 8; jj++) hrow[lane + jj * 32] = hsacc[jj] * 0.2f;
}

// ---------------- goW1/goW2 = go @ W1/W2 — warp per row --------------------
__global__ void goW12_kernel(const float* __restrict__ go,
                             const float* __restrict__ Wx_w,
                             float* __restrict__ gW1, float* __restrict__ gW2) {
    __shared__ float sW[2][ATT][5];
    int tid = threadIdx.x;
    for (int i = tid; i < 500; i += 256) {
        sW[0][i / 5][i % 5] = Wx_w[25 + i];
        sW[1][i / 5][i % 5] = Wx_w[525 + i];
    }
    __syncthreads();
    int warp = tid >> 5, lane = tid & 31;
    int row = blockIdx.x * 8 + warp;
    float4 g4 = make_float4(0.f, 0.f, 0.f, 0.f);
    int c0 = lane * 4;
    if (lane < 25) g4 = *reinterpret_cast<const float4*>(go + (long long)row * ATT + c0);
    #pragma unroll
    for (int kk = 0; kk < 5; kk++) {
        float s1 = 0.f, s2 = 0.f;
        if (lane < 25) {
            s1 = g4.x * sW[0][c0][kk] + g4.y * sW[0][c0 + 1][kk]
               + g4.z * sW[0][c0 + 2][kk] + g4.w * sW[0][c0 + 3][kk];
            s2 = g4.x * sW[1][c0][kk] + g4.y * sW[1][c0 + 1][kk]
               + g4.z * sW[1][c0 + 2][kk] + g4.w * sW[1][c0 + 3][kk];
        }
        #pragma unroll
        for (int o = 16; o > 0; o >>= 1) {
            s1 += __shfl_xor_sync(0xffffffffu, s1, o);
            s2 += __shfl_xor_sync(0xffffffffu, s2, o);
        }
        if (lane == 0) {
            gW1[(long long)row * 5 + kk] = s1;
            gW2[(long long)row * 5 + kk] = s2;
        }
    }
}

// ---------------- fused edge update + h-sum: hs = 0.2*sum_k(edge_k) -------
__global__ void edgehs_kernel(const float* __restrict__ adj,
                              const float* __restrict__ gW1,
                              const float* __restrict__ gW2,
                              const float* __restrict__ Wx_w,
                              const float* __restrict__ Wx_b,
                              float* __restrict__ hs) {
    __shared__ float Wa[25], bb[5];
    int t = threadIdx.x;
    if (t < 25) Wa[t] = Wx_w[t];
    if (t < 5)  bb[t] = Wx_b[t];
    __syncthreads();
    long long idx = (long long)blockIdx.x * 256 + t; // over B*L*L/4
    long long b = idx >> 14;
    long long ij4 = idx & 16383;
    const float4* ap = reinterpret_cast<const float4*>(adj) + b * 5 * 16384 + ij4;
    float aa[5][4];
    #pragma unroll
    for (int h = 0; h < Hh; h++) {
        float4 v = ap[(long long)h * 16384];
        aa[h][0] = v.x; aa[h][1] = v.y; aa[h][2] = v.z; aa[h][3] = v.w;
    }
    int i  = (int)(ij4 >> 6);
    int j0 = ((int)ij4 & 63) << 2;
    const float* g2 = gW2 + ((b << 8) + i) * 5;
    float g2r[5];
    #pragma unroll
    for (int kk = 0; kk < 5; kk++) g2r[kk] = g2[kk];
    float g1r[4][5];
    #pragma unroll
    for (int jj = 0; jj < 4; jj++) {
        const float* g1 = gW1 + ((b << 8) + j0 + jj) * 5;
        #pragma unroll
        for (int kk = 0; kk < 5; kk++) g1r[jj][kk] = g1[kk];
    }
    float outv[4] = {0.f, 0.f, 0.f, 0.f};
    #pragma unroll
    for (int kk = 0; kk < 5; kk++) {
        float base = bb[kk] + g2r[kk];
        #pragma unroll
        for (int jj = 0; jj < 4; jj++) {
            float v = base + g1r[jj][kk];
            #pragma unroll
            for (int h = 0; h < Hh; h++) v += aa[h][jj] * Wa[h * 5 + kk];
            outv[jj] += v;
        }
    }
    float4 o = make_float4(outv[0] * 0.2f, outv[1] * 0.2f, outv[2] * 0.2f, outv[3] * 0.2f);
    reinterpret_cast<float4*>(hs)[idx] = o;
}

// ---------------- final: aspect pool over relu(go2), then clf (parallel) ---
__global__ void final_kernel(const float* __restrict__ go,
                             const float* __restrict__ amask,
                             const float* __restrict__ clf_w,
                             const float* __restrict__ clf_b,
                             float* __restrict__ out) {
    int b = blockIdx.x;
    int t = threadIdx.x, w = t >> 5, lane = t & 31;
    __shared__ float part[8][104];
    __shared__ float o1[104];
    __shared__ float wred[8];

    float acc[4] = {0.f, 0.f, 0.f, 0.f};
    float wsum = 0.f;
    const float* gb_ = go + (long long)b * Ln * ATT;
    const float* mb = amask + b * Ln;
    for (int i = w * 32; i < w * 32 + 32; i++) {
        float m = mb[i];
        wsum += m;
        if (m != 0.f) {
            const float* gr = gb_ + (long long)i * ATT;
            #pragma unroll
            for (int c4 = 0; c4 < 4; c4++) {
                int c = lane + c4 * 32;
                if (c < ATT) acc[c4] += fmaxf(gr[c], 0.f) * m;
            }
        }
    }
    #pragma unroll
    for (int c4 = 0; c4 < 4; c4++) {
        int c = lane + c4 * 32;
        if (c < ATT) part[w][c] = acc[c4];
    }
    if (lane == 0) wred[w] = wsum;
    __syncthreads();
    if (t < ATT) {
        float s = 0.f;
        #pragma unroll
        for (int ww = 0; ww < 8; ww++) s += part[ww][t];
        o1[t] = s;
    }
    if (t == 0) {
        float s = 0.f;
        #pragma unroll
        for (int ww = 0; ww < 8; ww++) s += wred[ww];
        wred[0] = 1.f / s;
    }
    __syncthreads();
    float inv = wred[0];
    if (t < 3) {
        float s = clf_b[t];
        for (int c = 0; c < ATT; c++) s += o1[c] * inv * clf_w[c * 3 + t];
        out[b * 3 + t] = s;
    }
}

// ---------------- launch --------------------------------------------------
extern "C" void kernel_launch(void* const* d_in, const int* in_sizes, int n_in,
                              void* d_out, int out_size) {
    const float* seq     = (const float*)d_in[0];
    const int*   srcm    = (const int*)  d_in[1];
    const float* amask   = (const float*)d_in[2];
    const float* shortm  = (const float*)d_in[3];
    const float* ln_a    = (const float*)d_in[4];
    const float* ln_b    = (const float*)d_in[5];
    const float* Wxx_w   = (const float*)d_in[6];
    const float* Wxx_b   = (const float*)d_in[7];
    const float* q_w     = (const float*)d_in[8];
    const float* q_b     = (const float*)d_in[9];
    const float* k_w     = (const float*)d_in[10];
    const float* k_b     = (const float*)d_in[11];
    const float* dense_w = (const float*)d_in[12];
    const float* dense_b = (const float*)d_in[13];
    const float* bias_m  = (const float*)d_in[14];
    const float* W_w     = (const float*)d_in[15];
    const float* W_b     = (const float*)d_in[16];
    const float* Wx_w    = (const float*)d_in[17];
    const float* Wx_b    = (const float*)d_in[18];
    const float* clf_w   = (const float*)d_in[19];
    const float* clf_b   = (const float*)d_in[20];
    float* out = (float*)d_out;

    float* S = nullptr;
    cudaGetSymbolAddress((void**)&S, d_scratch);
    float* xln   = S + OFF_XLN;
    float* g     = S + OFF_G;
    float* q     = S + OFF_Q;
    float* k     = S + OFF_K;
    float* go    = S + OFF_GO;
    float* go2   = S + OFF_GO2;
    float* Ax    = S + OFF_AX;
    float* adj   = S + OFF_ADJ;
    float* hs    = S + OFF_HS;
    float* asp   = S + OFF_ASP;
    float* gW1   = S + OFF_GW1;
    float* gW2   = S + OFF_GW2;

    // 1. layernorm
    ln_kernel<<<NROW / 8, 256>>>(seq, ln_a, ln_b, xln);
    // 2. g = xln @ Wxx + b
    sgemm_kernel<<<dim3(NROW / BM, 2, 1), 256>>>(xln, Wxx_w, Wxx_b, g,
                                                 nullptr, nullptr, nullptr,
                                                 NROW, ATT, Dd, 0, 0, 0, 0);
    // 3. q and k projections in ONE launch
    sgemm_kernel<<<dim3(NROW / BM, 2, 2), 256>>>(g, q_w, q_b, q,
                                                 k_w, k_b, k,
                                                 NROW, ATT, ATT, 0, 0, 0, 0);
    // 4. aspect pool -> asp
    aspect_kernel<<<Bn, 256>>>(g, amask, dense_w, dense_b, asp);
    // 5. fused aspsc + scores + softmax -> adj, hs
    scores_fused_kernel<<<dim3(Ln / 8, Bn), 256>>>(q, k, asp, bias_m, srcm, shortm, adj, hs);

    // ---- GCN layer 0 ----
    sgemm_kernel<<<dim3(Ln / BM, 2, Bn), 256>>>(hs, g, nullptr, Ax,
                                                nullptr, nullptr, nullptr,
                                                Ln, ATT, Ln,
                                                (long long)Ln * Ln, (long long)Ln * ATT, (long long)Ln * ATT, 0);
    sgemm_kernel<<<dim3(NROW / BM, 2, 1), 256>>>(Ax, W_w, W_b, go,
                                                 nullptr, nullptr, nullptr,
                                                 NROW, ATT, ATT, 0, 0, 0, 1);
    // edge update fused with next hsum
    goW12_kernel<<<NROW / 8, 256>>>(go, Wx_w, gW1, gW2);
    edgehs_kernel<<<(Bn * Ln * Ln / 4) / 256, 256>>>(adj, gW1, gW2, Wx_w, Wx_b, hs);

    // ---- GCN layer 1 ----
    sgemm_kernel<<<dim3(Ln / BM, 2, Bn), 256>>>(hs, go, nullptr, Ax,
                                                nullptr, nullptr, nullptr,
                                                Ln, ATT, Ln,
                                                (long long)Ln * Ln, (long long)Ln * ATT, (long long)Ln * ATT, 0);
    sgemm_kernel<<<dim3(NROW / BM, 2, 1), 256>>>(Ax, W_w, W_b, go2,
                                                 nullptr, nullptr, nullptr,
                                                 NROW, ATT, ATT, 0, 0, 0, 1);

    // final
    final_kernel<<<Bn, 256>>>(go2, amask, clf_w, clf_b, out);
}

// round 4
// speedup vs baseline: 2.0225x; 1.1421x over previous
#include <cuda_runtime.h>
#include <math.h>

// ---------------- problem constants ----------------
#define Bn   32
#define Ln   256
#define Dd   768
#define ATT  100
#define Hh   5
#define DK   20
#define NROW (Bn*Ln)            // 8192

// ---------------- scratch (device globals; no cudaMalloc allowed) ----------
#define OFF_XLN   0ll
#define OFF_G     6291456ll
#define OFF_Q     7110656ll
#define OFF_K     7929856ll
#define OFF_GO    8749056ll
#define OFF_GO2   9568256ll
#define OFF_ADJ   11206656ll    // 32*5*256*256
#define OFF_WVEC  21692416ll    // w1s[128], w2s[128], wsum[8], sumbb[4]
#define OFF_ASP   23792768ll    // 32*20
#define OFF_SG1   23834368ll    // 8192
#define OFF_SG2   23875328ll
#define SCRATCH_TOTAL 23916288ll

__device__ __align__(16) float d_scratch[SCRATCH_TOTAL];

// ---------------- layernorm: one warp per row, one pass --------------------
__global__ void ln_kernel(const float* __restrict__ x,
                          const float* __restrict__ ga,
                          const float* __restrict__ gb,
                          float* __restrict__ out) {
    int warp = threadIdx.x >> 5, lane = threadIdx.x & 31;
    int row = blockIdx.x * 8 + warp;
    const float4* xr = reinterpret_cast<const float4*>(x + (long long)row * Dd);
    float4 v[6];
    float sum = 0.f, sq = 0.f;
    #pragma unroll
    for (int i = 0; i < 6; i++) {
        v[i] = xr[lane + i * 32];
        sum += v[i].x + v[i].y + v[i].z + v[i].w;
        sq  += v[i].x*v[i].x + v[i].y*v[i].y + v[i].z*v[i].z + v[i].w*v[i].w;
    }
    #pragma unroll
    for (int o = 16; o > 0; o >>= 1) {
        sum += __shfl_xor_sync(0xffffffffu, sum, o);
        sq  += __shfl_xor_sync(0xffffffffu, sq,  o);
    }
    float mean = sum * (1.f / (float)Dd);
    float var = (sq - (float)Dd * mean * mean) * (1.f / (float)(Dd - 1));
    float inv = 1.f / (sqrtf(var) + 1e-6f);
    const float4* gav = reinterpret_cast<const float4*>(ga);
    const float4* gbv = reinterpret_cast<const float4*>(gb);
    float4* outr = reinterpret_cast<float4*>(out + (long long)row * Dd);
    #pragma unroll
    for (int i = 0; i < 6; i++) {
        int idx = lane + i * 32;
        float4 a4 = gav[idx], b4 = gbv[idx], o4;
        o4.x = a4.x * (v[i].x - mean) * inv + b4.x;
        o4.y = a4.y * (v[i].y - mean) * inv + b4.y;
        o4.z = a4.z * (v[i].z - mean) * inv + b4.z;
        o4.w = a4.w * (v[i].w - mean) * inv + b4.w;
        outr[idx] = o4;
    }
}

// ---------------- double-buffered SGEMM (for g and q/k projections) -------
#define BM 64
#define BN 64
#define BK 16
__global__ __launch_bounds__(256, 4)
void sgemm_kernel(const float* __restrict__ A,
                  const float* __restrict__ B0, const float* __restrict__ bias0, float* __restrict__ C0,
                  const float* __restrict__ B1, const float* __restrict__ bias1, float* __restrict__ C1,
                  int M, int N, int K) {
    const float* Bw; const float* bias; float* C;
    if (B1 != nullptr && blockIdx.z == 1) { Bw = B1; bias = bias1; C = C1; }
    else                                  { Bw = B0; bias = bias0; C = C0; }

    __shared__ __align__(16) float As[2][BK][BM + 4];
    __shared__ __align__(16) float Bs[2][BK][BN + 4];

    int tid = threadIdx.x;
    int tx = tid & 15, ty = tid >> 4;
    int m0 = blockIdx.x * BM, n0 = blockIdx.y * BN;

    int ar = tid >> 2;
    int ac = (tid & 3) << 2;
    int br = tid >> 4;
    int bc = (tid & 15) << 2;

    const float* Arow = A + (long long)(m0 + ar) * K;
    int bn = n0 + bc;
    bool bnok = (bn < N);

    float acc[4][4] = {};
    float4 aR, bR;
    const float4 z4 = make_float4(0.f, 0.f, 0.f, 0.f);

    int nt = (K + BK - 1) / BK;
    {
        int ka = ac, kb = br;
        aR = (ka < K) ? *reinterpret_cast<const float4*>(Arow + ka) : z4;
        bR = (kb < K && bnok) ? *reinterpret_cast<const float4*>(Bw + (long long)kb * N + bn) : z4;
    }
    int s = 0;
    for (int t = 0; t < nt; t++) {
        As[s][ac + 0][ar] = aR.x;
        As[s][ac + 1][ar] = aR.y;
        As[s][ac + 2][ar] = aR.z;
        As[s][ac + 3][ar] = aR.w;
        *reinterpret_cast<float4*>(&Bs[s][br][bc]) = bR;
        __syncthreads();
        if (t + 1 < nt) {
            int ka = (t + 1) * BK + ac;
            int kb = (t + 1) * BK + br;
            aR = (ka < K) ? *reinterpret_cast<const float4*>(Arow + ka) : z4;
            bR = (kb < K && bnok) ? *reinterpret_cast<const float4*>(Bw + (long long)kb * N + bn) : z4;
        }
        #pragma unroll
        for (int kk = 0; kk < BK; kk++) {
            float4 a4 = *reinterpret_cast<const float4*>(&As[s][kk][ty * 4]);
            float4 b4 = *reinterpret_cast<const float4*>(&Bs[s][kk][tx * 4]);
            acc[0][0] += a4.x * b4.x; acc[0][1] += a4.x * b4.y; acc[0][2] += a4.x * b4.z; acc[0][3] += a4.x * b4.w;
            acc[1][0] += a4.y * b4.x; acc[1][1] += a4.y * b4.y; acc[1][2] += a4.y * b4.z; acc[1][3] += a4.y * b4.w;
            acc[2][0] += a4.z * b4.x; acc[2][1] += a4.z * b4.y; acc[2][2] += a4.z * b4.z; acc[2][3] += a4.z * b4.w;
            acc[3][0] += a4.w * b4.x; acc[3][1] += a4.w * b4.y; acc[3][2] += a4.w * b4.z; acc[3][3] += a4.w * b4.w;
        }
        s ^= 1;
        __syncthreads();
    }

    int gn0 = n0 + tx * 4;
    float bv[4] = {0.f, 0.f, 0.f, 0.f};
    if (bias) {
        #pragma unroll
        for (int j = 0; j < 4; j++) if (gn0 + j < N) bv[j] = bias[gn0 + j];
    }
    #pragma unroll
    for (int i = 0; i < 4; i++) {
        int gm = m0 + ty * 4 + i;
        float* crow = C + (long long)gm * N;
        float v[4];
        #pragma unroll
        for (int j = 0; j < 4; j++) v[j] = acc[i][j] + bv[j];
        if (gn0 + 3 < N) {
            *reinterpret_cast<float4*>(crow + gn0) = make_float4(v[0], v[1], v[2], v[3]);
        } else {
            #pragma unroll
            for (int j = 0; j < 4; j++) if (gn0 + j < N) crow[gn0 + j] = v[j];
        }
    }
}

// ---------------- prep: column-sum vectors of Wx_w --------------------------
// wvec layout: [0..99]=w1s, [128..227]=w2s, [256..260]=wsum, [264]=sumbb
__global__ void prep_kernel(const float* __restrict__ Wx_w,
                            const float* __restrict__ Wx_b,
                            float* __restrict__ wvec) {
    int t = threadIdx.x; // 128
    if (t < ATT) {
        float s1 = 0.f, s2 = 0.f;
        #pragma unroll
        for (int k = 0; k < 5; k++) {
            s1 += Wx_w[(5 + t) * 5 + k];
            s2 += Wx_w[(105 + t) * 5 + k];
        }
        wvec[t] = s1;
        wvec[128 + t] = s2;
    }
    if (t >= 100 && t < 105) {
        int h = t - 100;
        float s = 0.f;
        #pragma unroll
        for (int k = 0; k < 5; k++) s += Wx_w[h * 5 + k];
        wvec[256 + h] = s;
    }
    if (t == 105) {
        float s = 0.f;
        #pragma unroll
        for (int k = 0; k < 5; k++) s += Wx_b[k];
        wvec[264] = s;
    }
}

// ---------------- aspect pooling + asp (smem mask, no LDG-dependent branch)
__global__ void aspect_kernel(const float* __restrict__ g,
                              const float* __restrict__ amask,
                              const float* __restrict__ dense_w,
                              const float* __restrict__ dense_b,
                              float* __restrict__ asp) {
    int b = blockIdx.x;
    int t = threadIdx.x, w = t >> 5, lane = t & 31;
    __shared__ float smask[Ln];
    __shared__ float part[8][104];
    __shared__ float sa[104];
    __shared__ float wred[8];

    smask[t] = amask[b * Ln + t];
    __syncthreads();

    float acc[4] = {0.f, 0.f, 0.f, 0.f};
    float wsum = 0.f;
    const float* gb_ = g + (long long)b * Ln * ATT;
    for (int i = w * 32; i < w * 32 + 32; i++) {
        float m = smask[i];
        wsum += m;
        if (m != 0.f) {
            const float* gr = gb_ + (long long)i * ATT;
            #pragma unroll
            for (int c4 = 0; c4 < 4; c4++) {
                int c = lane + c4 * 32;
                if (c < ATT) acc[c4] += gr[c] * m;
            }
        }
    }
    #pragma unroll
    for (int c4 = 0; c4 < 4; c4++) {
        int c = lane + c4 * 32;
        if (c < ATT) part[w][c] = acc[c4];
    }
    if (lane == 0) wred[w] = wsum;
    __syncthreads();
    if (t < ATT) {
        float s = 0.f;
        #pragma unroll
        for (int ww = 0; ww < 8; ww++) s += part[ww][t];
        sa[t] = s;
    }
    if (t == 0) {
        float s = 0.f;
        #pragma unroll
        for (int ww = 0; ww < 8; ww++) s += wred[ww];
        wred[0] = 1.f / s;
    }
    __syncthreads();
    float inv = wred[0];
    if (t < DK) {
        float s = dense_b[t];
        for (int c = 0; c < ATT; c++) s += sa[c] * inv * dense_w[c * DK + t];
        asp[b * DK + t] = s;
    }
}

// ---- scores + aspsc + mask + softmax -> adj (per-(b,h) parallelism) -------
__global__ __launch_bounds__(256, 4)
void scores_kernel(const float* __restrict__ q,
                   const float* __restrict__ k,
                   const float* __restrict__ asp,
                   const float* __restrict__ bias_m,
                   const int*   __restrict__ src_mask,
                   const float* __restrict__ short_mask,
                   float* __restrict__ adj) {
    int it = blockIdx.x, h = blockIdx.y, b = blockIdx.z;
    __shared__ float kt[Ln][21];
    __shared__ float addv[Ln];
    __shared__ float qs[8][20];
    __shared__ float sasp[DK];
    __shared__ int   msk[Ln];
    int t = threadIdx.x, w = t >> 5, lane = t & 31;
    int i = it * 8 + w;

    if (t < DK) sasp[t] = asp[b * DK + t];
    msk[t] = src_mask[b * Ln + t];
    {
        const float4* kr = reinterpret_cast<const float4*>(
            k + ((long long)b * Ln + t) * ATT + h * DK);
        #pragma unroll
        for (int f = 0; f < 5; f++) {
            float4 v = kr[f];
            kt[t][f * 4 + 0] = v.x;
            kt[t][f * 4 + 1] = v.y;
            kt[t][f * 4 + 2] = v.z;
            kt[t][f * 4 + 3] = v.w;
        }
    }
    if (t < 160) {
        int r = t / 20, d = t % 20;
        qs[r][d] = q[((long long)b * Ln + it * 8 + r) * ATT + h * DK + d];
    }
    __syncthreads();
    {
        float s = 0.f;
        #pragma unroll
        for (int d = 0; d < DK; d++) s += sasp[d] * kt[t][d];
        addv[t] = tanhf(s + bias_m[0]);
    }
    __syncthreads();

    const float* srow = short_mask + ((long long)b * Ln + i) * Ln;
    float sc[8] = {0.f, 0.f, 0.f, 0.f, 0.f, 0.f, 0.f, 0.f};
    #pragma unroll
    for (int d = 0; d < DK; d++) {
        float qd = qs[w][d];
        #pragma unroll
        for (int jj = 0; jj < 8; jj++)
            sc[jj] += qd * kt[lane + jj * 32][d];
    }
    const float rsd = 0.22360679774997896f; // 1/sqrt(20)
    float mx = -3.4e38f;
    #pragma unroll
    for (int jj = 0; jj < 8; jj++) {
        int j = lane + jj * 32;
        float v = sc[jj] * rsd + addv[j];
        if (msk[j] == 0) v = -1e9f;
        v += srow[j];
        sc[jj] = v;
        mx = fmaxf(mx, v);
    }
    #pragma unroll
    for (int o = 16; o > 0; o >>= 1) mx = fmaxf(mx, __shfl_xor_sync(0xffffffffu, mx, o));
    float sum = 0.f;
    #pragma unroll
    for (int jj = 0; jj < 8; jj++) { sc[jj] = expf(sc[jj] - mx); sum += sc[jj]; }
    #pragma unroll
    for (int o = 16; o > 0; o >>= 1) sum += __shfl_xor_sync(0xffffffffu, sum, o);
    float invs = 1.f / sum;
    float* arow = adj + (((long long)(b * Hh + h)) * Ln + i) * Ln;
    #pragma unroll
    for (int jj = 0; jj < 8; jj++) arow[lane + jj * 32] = sc[jj] * invs;
}

// ---------------- fused GCN layer: out = relu((A' @ Bsrc_b) @ W_w + W_b) ---
// A' per mode:  mode 0 (layer 0):  A'[i,j] = 0.2 * sum_h adj[b,h,i,j]
//               mode 1 (layer 1):  A'[i,j] = 0.2 * (sumbb + sg1[b,j] + sg2[b,i]
//                                            + sum_h adj[b,h,i,j]*wsum[h])
// mode 0 additionally writes sg1o[row] = go_row . w1s, sg2o[row] = go_row . w2s
// grid (Ln/64, 1, Bn), 320 threads: tx=tid%20 (5 cols), ty=tid/20 (4 rows)
__global__ __launch_bounds__(320, 2)
void gcn_layer_kernel(const float* __restrict__ adj,
                      const float* __restrict__ Bsrc,
                      const float* __restrict__ W_w,
                      const float* __restrict__ W_b,
                      const float* __restrict__ sg1,
                      const float* __restrict__ sg2,
                      const float* __restrict__ wvec,
                      float* __restrict__ outC,
                      float* __restrict__ sg1o,
                      float* __restrict__ sg2o,
                      int mode) {
    __shared__ __align__(16) float As[2][16][68];
    __shared__ __align__(16) float Bs[2][16][104];
    __shared__ __align__(16) float AxS[64][101];

    int b = blockIdx.z;
    int m0 = blockIdx.x * 64;
    int tid = threadIdx.x;
    int tx = tid % 20, ty = tid / 20;
    int tx5 = tx * 5, ty4 = ty * 4;

    const float* adjb = adj + (long long)b * Hh * 65536;
    const float* Bb   = Bsrc + (long long)b * (Ln * ATT);

    float ws0 = 0.f, ws1 = 0.f, ws2 = 0.f, ws3 = 0.f, ws4 = 0.f, sbb = 0.f;
    if (mode == 1) {
        ws0 = wvec[256]; ws1 = wvec[257]; ws2 = wvec[258];
        ws3 = wvec[259]; ws4 = wvec[260]; sbb = wvec[264];
    }

    int ar = tid >> 2, ac = (tid & 3) << 2;       // A loader (tid<256)
    bool aok = (tid < 256);
    int bi0 = tid;                                 // B loader item 0 (always <400)
    int bi1 = tid + 320;                           // B loader item 1 (<400 iff tid<80)
    bool b1ok = (bi1 < 400);
    int b0r = bi0 / 25, b0c = (bi0 % 25) * 4;
    int b1r = bi1 / 25, b1c = (bi1 % 25) * 4;

    float acc[4][5];
    #pragma unroll
    for (int i = 0; i < 4; i++)
        #pragma unroll
        for (int j = 0; j < 5; j++) acc[i][j] = 0.f;

    float4 aR = make_float4(0.f, 0.f, 0.f, 0.f);
    float4 bR0 = aR, bR1 = aR;

    // ---- A tile prefetch helper (manually inlined twice) ----
    #define LOAD_A(k0)                                                          \
        do {                                                                    \
            const float* basep = adjb + (long long)(m0 + ar) * 256 + ((k0) + ac); \
            float4 s_ = make_float4(0.f, 0.f, 0.f, 0.f);                        \
            if (mode == 0) {                                                    \
                _Pragma("unroll")                                               \
                for (int h_ = 0; h_ < 5; h_++) {                                \
                    float4 v_ = *reinterpret_cast<const float4*>(basep + h_ * 65536); \
                    s_.x += v_.x; s_.y += v_.y; s_.z += v_.z; s_.w += v_.w;     \
                }                                                               \
                s_.x *= 0.2f; s_.y *= 0.2f; s_.z *= 0.2f; s_.w *= 0.2f;         \
            } else {                                                            \
                float wsv_[5] = {ws0, ws1, ws2, ws3, ws4};                      \
                _Pragma("unroll")                                               \
                for (int h_ = 0; h_ < 5; h_++) {                                \
                    float4 v_ = *reinterpret_cast<const float4*>(basep + h_ * 65536); \
                    s_.x += v_.x * wsv_[h_]; s_.y += v_.y * wsv_[h_];           \
                    s_.z += v_.z * wsv_[h_]; s_.w += v_.w * wsv_[h_];           \
                }                                                               \
                float4 s1_ = *reinterpret_cast<const float4*>(sg1 + b * 256 + (k0) + ac); \
                float s2_ = sg2[b * 256 + m0 + ar];                             \
                float c_ = sbb + s2_;                                           \
                s_.x = 0.2f * (s_.x + c_ + s1_.x);                              \
                s_.y = 0.2f * (s_.y + c_ + s1_.y);                              \
                s_.z = 0.2f * (s_.z + c_ + s1_.z);                              \
                s_.w = 0.2f * (s_.w + c_ + s1_.w);                              \
            }                                                                   \
            aR = s_;                                                            \
        } while (0)

    // prefetch tile 0
    if (aok) LOAD_A(0);
    bR0 = *reinterpret_cast<const float4*>(Bb + (long long)b0r * ATT + b0c);
    if (b1ok) bR1 = *reinterpret_cast<const float4*>(Bb + (long long)b1r * ATT + b1c);

    int s = 0;
    for (int t = 0; t < 16; t++) {
        if (aok) {
            As[s][ac + 0][ar] = aR.x;
            As[s][ac + 1][ar] = aR.y;
            As[s][ac + 2][ar] = aR.z;
            As[s][ac + 3][ar] = aR.w;
        }
        *reinterpret_cast<float4*>(&Bs[s][b0r][b0c]) = bR0;
        if (b1ok) *reinterpret_cast<float4*>(&Bs[s][b1r][b1c]) = bR1;
        __syncthreads();
        if (t + 1 < 16) {
            int k0 = (t + 1) * 16;
            if (aok) LOAD_A(k0);
            bR0 = *reinterpret_cast<const float4*>(Bb + (long long)(k0 + b0r) * ATT + b0c);
            if (b1ok) bR1 = *reinterpret_cast<const float4*>(Bb + (long long)(k0 + b1r) * ATT + b1c);
        }
        #pragma unroll
        for (int kk = 0; kk < 16; kk++) {
            float4 a4 = *reinterpret_cast<const float4*>(&As[s][kk][ty4]);
            float b0 = Bs[s][kk][tx5 + 0];
            float b1 = Bs[s][kk][tx5 + 1];
            float b2 = Bs[s][kk][tx5 + 2];
            float b3 = Bs[s][kk][tx5 + 3];
            float b4 = Bs[s][kk][tx5 + 4];
            acc[0][0] += a4.x * b0; acc[0][1] += a4.x * b1; acc[0][2] += a4.x * b2; acc[0][3] += a4.x * b3; acc[0][4] += a4.x * b4;
            acc[1][0] += a4.y * b0; acc[1][1] += a4.y * b1; acc[1][2] += a4.y * b2; acc[1][3] += a4.y * b3; acc[1][4] += a4.y * b4;
            acc[2][0] += a4.z * b0; acc[2][1] += a4.z * b1; acc[2][2] += a4.z * b2; acc[2][3] += a4.z * b3; acc[2][4] += a4.z * b4;
            acc[3][0] += a4.w * b0; acc[3][1] += a4.w * b1; acc[3][2] += a4.w * b2; acc[3][3] += a4.w * b3; acc[3][4] += a4.w * b4;
        }
        s ^= 1;
        __syncthreads();
    }
    #undef LOAD_A

    // stash Ax tile in smem
    #pragma unroll
    for (int i = 0; i < 4; i++)
        #pragma unroll
        for (int j = 0; j < 5; j++)
            AxS[ty4 + i][tx5 + j] = acc[i][j];

    // second GEMM: acc2 = AxS @ W_w  (K2 = 100)
    float acc2[4][5];
    #pragma unroll
    for (int i = 0; i < 4; i++)
        #pragma unroll
        for (int j = 0; j < 5; j++) acc2[i][j] = 0.f;

    for (int k2 = 0; k2 < ATT; k2 += 16) {
        int kmax = ATT - k2; if (kmax > 16) kmax = 16;
        __syncthreads();
        for (int i = tid; i < 400; i += 320) {
            int row = i / 25, c4 = (i % 25) * 4;
            float4 v = make_float4(0.f, 0.f, 0.f, 0.f);
            if (row < kmax) v = *reinterpret_cast<const float4*>(W_w + (long long)(k2 + row) * ATT + c4);
            *reinterpret_cast<float4*>(&Bs[0][row][c4]) = v;
        }
        __syncthreads();
        for (int kk = 0; kk < kmax; kk++) {
            float a0 = AxS[ty4 + 0][k2 + kk];
            float a1 = AxS[ty4 + 1][k2 + kk];
            float a2 = AxS[ty4 + 2][k2 + kk];
            float a3 = AxS[ty4 + 3][k2 + kk];
            float b0 = Bs[0][kk][tx5 + 0];
            float b1 = Bs[0][kk][tx5 + 1];
            float b2 = Bs[0][kk][tx5 + 2];
            float b3 = Bs[0][kk][tx5 + 3];
            float b4 = Bs[0][kk][tx5 + 4];
            acc2[0][0] += a0 * b0; acc2[0][1] += a0 * b1; acc2[0][2] += a0 * b2; acc2[0][3] += a0 * b3; acc2[0][4] += a0 * b4;
            acc2[1][0] += a1 * b0; acc2[1][1] += a1 * b1; acc2[1][2] += a1 * b2; acc2[1][3] += a1 * b3; acc2[1][4] += a1 * b4;
            acc2[2][0] += a2 * b0; acc2[2][1] += a2 * b1; acc2[2][2] += a2 * b2; acc2[2][3] += a2 * b3; acc2[2][4] += a2 * b4;
            acc2[3][0] += a3 * b0; acc2[3][1] += a3 * b1; acc2[3][2] += a3 * b2; acc2[3][3] += a3 * b3; acc2[3][4] += a3 * b4;
        }
    }

    // epilogue: bias + relu + store, plus sg1/sg2 partials in mode 0
    float wb[5], w1r[5], w2r[5];
    #pragma unroll
    for (int j = 0; j < 5; j++) wb[j] = W_b[tx5 + j];
    if (mode == 0) {
        #pragma unroll
        for (int j = 0; j < 5; j++) { w1r[j] = wvec[tx5 + j]; w2r[j] = wvec[128 + tx5 + j]; }
    }
    float p1[4] = {0.f, 0.f, 0.f, 0.f}, p2[4] = {0.f, 0.f, 0.f, 0.f};
    #pragma unroll
    for (int i = 0; i < 4; i++) {
        int gm = m0 + ty4 + i;
        float* crow = outC + ((long long)b * Ln + gm) * ATT;
        #pragma unroll
        for (int j = 0; j < 5; j++) {
            float v = fmaxf(acc2[i][j] + wb[j], 0.f);
            crow[tx5 + j] = v;
            if (mode == 0) { p1[i] += v * w1r[j]; p2[i] += v * w2r[j]; }
        }
    }

    if (mode == 0) {
        __syncthreads();   // AxS reads done; safe to overwrite
        #pragma unroll
        for (int i = 0; i < 4; i++) {
            AxS[ty4 + i][tx]      = p1[i];
            AxS[ty4 + i][20 + tx] = p2[i];
        }
        __syncthreads();
        if (tid < 64) {
            float s1 = 0.f, s2 = 0.f;
            #pragma unroll
            for (int x = 0; x < 20; x++) { s1 += AxS[tid][x]; s2 += AxS[tid][20 + x]; }
            sg1o[b * 256 + m0 + tid] = s1;
            sg2o[b * 256 + m0 + tid] = s2;
        }
    }
}

// ---------------- final: aspect pool over relu(go2), then clf -------------
__global__ void final_kernel(const float* __restrict__ go,
                             const float* __restrict__ amask,
                             const float* __restrict__ clf_w,
                             const float* __restrict__ clf_b,
                             float* __restrict__ out) {
    int b = blockIdx.x;
    int t = threadIdx.x, w = t >> 5, lane = t & 31;
    __shared__ float smask[Ln];
    __shared__ float part[8][104];
    __shared__ float o1[104];
    __shared__ float wred[8];

    smask[t] = amask[b * Ln + t];
    __syncthreads();

    float acc[4] = {0.f, 0.f, 0.f, 0.f};
    float wsum = 0.f;
    const float* gb_ = go + (long long)b * Ln * ATT;
    for (int i = w * 32; i < w * 32 + 32; i++) {
        float m = smask[i];
        wsum += m;
        if (m != 0.f) {
            const float* gr = gb_ + (long long)i * ATT;
            #pragma unroll
            for (int c4 = 0; c4 < 4; c4++) {
                int c = lane + c4 * 32;
                if (c < ATT) acc[c4] += fmaxf(gr[c], 0.f) * m;
            }
        }
    }
    #pragma unroll
    for (int c4 = 0; c4 < 4; c4++) {
        int c = lane + c4 * 32;
        if (c < ATT) part[w][c] = acc[c4];
    }
    if (lane == 0) wred[w] = wsum;
    __syncthreads();
    if (t < ATT) {
        float s = 0.f;
        #pragma unroll
        for (int ww = 0; ww < 8; ww++) s += part[ww][t];
        o1[t] = s;
    }
    if (t == 0) {
        float s = 0.f;
        #pragma unroll
        for (int ww = 0; ww < 8; ww++) s += wred[ww];
        wred[0] = 1.f / s;
    }
    __syncthreads();
    float inv = wred[0];
    if (t < 3) {
        float s = clf_b[t];
        for (int c = 0; c < ATT; c++) s += o1[c] * inv * clf_w[c * 3 + t];
        out[b * 3 + t] = s;
    }
}

// ---------------- launch --------------------------------------------------
extern "C" void kernel_launch(void* const* d_in, const int* in_sizes, int n_in,
                              void* d_out, int out_size) {
    const float* seq     = (const float*)d_in[0];
    const int*   srcm    = (const int*)  d_in[1];
    const float* amask   = (const float*)d_in[2];
    const float* shortm  = (const float*)d_in[3];
    const float* ln_a    = (const float*)d_in[4];
    const float* ln_b    = (const float*)d_in[5];
    const float* Wxx_w   = (const float*)d_in[6];
    const float* Wxx_b   = (const float*)d_in[7];
    const float* q_w     = (const float*)d_in[8];
    const float* q_b     = (const float*)d_in[9];
    const float* k_w     = (const float*)d_in[10];
    const float* k_b     = (const float*)d_in[11];
    const float* dense_w = (const float*)d_in[12];
    const float* dense_b = (const float*)d_in[13];
    const float* bias_m  = (const float*)d_in[14];
    const float* W_w     = (const float*)d_in[15];
    const float* W_b     = (const float*)d_in[16];
    const float* Wx_w    = (const float*)d_in[17];
    const float* Wx_b    = (const float*)d_in[18];
    const float* clf_w   = (const float*)d_in[19];
    const float* clf_b   = (const float*)d_in[20];
    float* out = (float*)d_out;

    float* S = nullptr;
    cudaGetSymbolAddress((void**)&S, d_scratch);
    float* xln   = S + OFF_XLN;
    float* g     = S + OFF_G;
    float* q     = S + OFF_Q;
    float* k     = S + OFF_K;
    float* go    = S + OFF_GO;
    float* go2   = S + OFF_GO2;
    float* adj   = S + OFF_ADJ;
    float* wvec  = S + OFF_WVEC;
    float* asp   = S + OFF_ASP;
    float* sg1   = S + OFF_SG1;
    float* sg2   = S + OFF_SG2;

    // 1. layernorm
    ln_kernel<<<NROW / 8, 256>>>(seq, ln_a, ln_b, xln);
    // 2. g = xln @ Wxx + b
    sgemm_kernel<<<dim3(NROW / BM, 2, 1), 256>>>(xln, Wxx_w, Wxx_b, g,
                                                 nullptr, nullptr, nullptr,
                                                 NROW, ATT, Dd);
    // 3. q and k projections in ONE launch
    sgemm_kernel<<<dim3(NROW / BM, 2, 2), 256>>>(g, q_w, q_b, q,
                                                 k_w, k_b, k,
                                                 NROW, ATT, ATT);
    // 4. aspect pool -> asp ; prep Wx column sums
    aspect_kernel<<<Bn, 256>>>(g, amask, dense_w, dense_b, asp);
    prep_kernel<<<1, 128>>>(Wx_w, Wx_b, wvec);
    // 5. scores + softmax -> adj (per-head parallel)
    scores_kernel<<<dim3(Ln / 8, Hh, Bn), 256>>>(q, k, asp, bias_m, srcm, shortm, adj);

    // 6. GCN layer 0 (fused: mean_h adj @ g @ W_w, relu, sg1/sg2)
    gcn_layer_kernel<<<dim3(Ln / 64, 1, Bn), 320>>>(adj, g, W_w, W_b,
                                                    nullptr, nullptr, wvec,
                                                    go, sg1, sg2, 0);
    // 7. GCN layer 1 (fused: edge-collapsed adj @ go @ W_w, relu)
    gcn_layer_kernel<<<dim3(Ln / 64, 1, Bn), 320>>>(adj, go, W_w, W_b,
                                                    sg1, sg2, wvec,
                                                    go2, nullptr, nullptr, 1);

    // 8. final
    final_kernel<<<Bn, 256>>>(go2, amask, clf_w, clf_b, out);
}

// round 5
// speedup vs baseline: 2.1501x; 1.0631x over previous
#include <cuda_runtime.h>
#include <math.h>

// ---------------- problem constants ----------------
#define Bn   32
#define Ln   256
#define Dd   768
#define ATT  100
#define Hh   5
#define DK   20
#define NROW (Bn*Ln)            // 8192

// ---------------- scratch ----------------
#define OFF_G     6291456ll
#define OFF_Q     7110656ll
#define OFF_K     7929856ll
#define OFF_GO    8749056ll
#define OFF_ADJ   11206656ll    // 32*5*256*256
#define OFF_ASP   23792768ll    // 32*20
#define OFF_SG1   23834368ll    // 8192
#define OFF_SG2   23875328ll
#define SCRATCH_TOTAL 23916288ll

__device__ __align__(16) float d_scratch[SCRATCH_TOTAL];

// =====================================================================
// 1. Fused LayerNorm + GEMM:  g = LN(x) @ Wxx_w + Wxx_b
//    grid NROW/64, 320 threads. BM=64, BN=100 (full), BK=16, K=768.
// =====================================================================
__global__ __launch_bounds__(320, 2)
void lng_kernel(const float* __restrict__ x,
                const float* __restrict__ ga,
                const float* __restrict__ gb,
                const float* __restrict__ Ww,
                const float* __restrict__ Wb,
                float* __restrict__ g) {
    __shared__ __align__(16) float As[2][16][68];
    __shared__ __align__(16) float Bs[2][16][104];
    __shared__ float smean[64], sinv[64];

    int tid = threadIdx.x;
    int m0 = blockIdx.x * 64;
    int w = tid >> 5, lane = tid & 31;

    // ---- LN stats pre-pass: warps 0..7, 8 rows each ----
    if (w < 8) {
        #pragma unroll
        for (int r = 0; r < 8; r++) {
            int row = w * 8 + r;
            const float4* xr = reinterpret_cast<const float4*>(x + (long long)(m0 + row) * Dd);
            float sum = 0.f, sq = 0.f;
            #pragma unroll
            for (int i = 0; i < 6; i++) {
                float4 v = xr[lane + i * 32];
                sum += v.x + v.y + v.z + v.w;
                sq  += v.x*v.x + v.y*v.y + v.z*v.z + v.w*v.w;
            }
            #pragma unroll
            for (int o = 16; o > 0; o >>= 1) {
                sum += __shfl_xor_sync(0xffffffffu, sum, o);
                sq  += __shfl_xor_sync(0xffffffffu, sq,  o);
            }
            if (lane == 0) {
                float mean = sum * (1.f / (float)Dd);
                float var = (sq - (float)Dd * mean * mean) * (1.f / (float)(Dd - 1));
                smean[row] = mean;
                sinv[row] = 1.f / (sqrtf(var) + 1e-6f);
            }
        }
    }
    __syncthreads();

    int tx = tid % 20, ty = tid / 20;
    int tx5 = tx * 5, ty4 = ty * 4;

    bool aok = (tid < 256);
    int ar = tid >> 2, ac = (tid & 3) << 2;
    int b0r = tid / 25, b0c = (tid % 25) * 4;
    int bi1 = tid + 320;
    bool b1ok = (bi1 < 400);
    int b1r = bi1 / 25, b1c = (bi1 % 25) * 4;

    const float* Xrow = x + (long long)(m0 + ar) * Dd;
    float meanv = 0.f, invv = 0.f;
    if (aok) { meanv = smean[ar]; invv = sinv[ar]; }

    float acc[4][5];
    #pragma unroll
    for (int i = 0; i < 4; i++)
        #pragma unroll
        for (int j = 0; j < 5; j++) acc[i][j] = 0.f;

    float4 aR = make_float4(0.f,0.f,0.f,0.f), bR0 = aR, bR1 = aR;

    #define LOAD_LNA(k0)                                                 \
        do {                                                             \
            float4 x4 = *reinterpret_cast<const float4*>(Xrow + (k0) + ac);   \
            float4 ga4 = *reinterpret_cast<const float4*>(ga + (k0) + ac);    \
            float4 gb4 = *reinterpret_cast<const float4*>(gb + (k0) + ac);    \
            aR.x = ga4.x * (x4.x - meanv) * invv + gb4.x;                \
            aR.y = ga4.y * (x4.y - meanv) * invv + gb4.y;                \
            aR.z = ga4.z * (x4.z - meanv) * invv + gb4.z;                \
            aR.w = ga4.w * (x4.w - meanv) * invv + gb4.w;                \
        } while (0)

    if (aok) LOAD_LNA(0);
    bR0 = *reinterpret_cast<const float4*>(Ww + (long long)b0r * ATT + b0c);
    if (b1ok) bR1 = *reinterpret_cast<const float4*>(Ww + (long long)b1r * ATT + b1c);

    int s = 0;
    for (int t = 0; t < 48; t++) {
        if (aok) {
            As[s][ac + 0][ar] = aR.x;
            As[s][ac + 1][ar] = aR.y;
            As[s][ac + 2][ar] = aR.z;
            As[s][ac + 3][ar] = aR.w;
        }
        *reinterpret_cast<float4*>(&Bs[s][b0r][b0c]) = bR0;
        if (b1ok) *reinterpret_cast<float4*>(&Bs[s][b1r][b1c]) = bR1;
        __syncthreads();
        if (t + 1 < 48) {
            int k0 = (t + 1) * 16;
            if (aok) LOAD_LNA(k0);
            bR0 = *reinterpret_cast<const float4*>(Ww + (long long)(k0 + b0r) * ATT + b0c);
            if (b1ok) bR1 = *reinterpret_cast<const float4*>(Ww + (long long)(k0 + b1r) * ATT + b1c);
        }
        #pragma unroll
        for (int kk = 0; kk < 16; kk++) {
            float4 a4 = *reinterpret_cast<const float4*>(&As[s][kk][ty4]);
            float b0 = Bs[s][kk][tx5 + 0];
            float b1 = Bs[s][kk][tx5 + 1];
            float b2 = Bs[s][kk][tx5 + 2];
            float b3 = Bs[s][kk][tx5 + 3];
            float b4 = Bs[s][kk][tx5 + 4];
            acc[0][0] += a4.x*b0; acc[0][1] += a4.x*b1; acc[0][2] += a4.x*b2; acc[0][3] += a4.x*b3; acc[0][4] += a4.x*b4;
            acc[1][0] += a4.y*b0; acc[1][1] += a4.y*b1; acc[1][2] += a4.y*b2; acc[1][3] += a4.y*b3; acc[1][4] += a4.y*b4;
            acc[2][0] += a4.z*b0; acc[2][1] += a4.z*b1; acc[2][2] += a4.z*b2; acc[2][3] += a4.z*b3; acc[2][4] += a4.z*b4;
            acc[3][0] += a4.w*b0; acc[3][1] += a4.w*b1; acc[3][2] += a4.w*b2; acc[3][3] += a4.w*b3; acc[3][4] += a4.w*b4;
        }
        s ^= 1;
        __syncthreads();
    }
    #undef LOAD_LNA

    float wb[5];
    #pragma unroll
    for (int j = 0; j < 5; j++) wb[j] = Wb[tx5 + j];
    #pragma unroll
    for (int i = 0; i < 4; i++) {
        float* crow = g + (long long)(m0 + ty4 + i) * ATT;
        #pragma unroll
        for (int j = 0; j < 5; j++) crow[tx5 + j] = acc[i][j] + wb[j];
    }
}

// =====================================================================
// 2. Merged launch: q/k projections (GEMM K=100) + aspect pooling
//    grid 288 blocks x 320 threads.
//    blk <128: q tile | 128..255: k tile | 256..287: aspect for b=blk-256
// =====================================================================
__global__ __launch_bounds__(320, 2)
void qkaspect_kernel(const float* __restrict__ g,
                     const float* __restrict__ q_w, const float* __restrict__ q_b,
                     const float* __restrict__ k_w, const float* __restrict__ k_b,
                     const float* __restrict__ amask,
                     const float* __restrict__ dense_w,
                     const float* __restrict__ dense_b,
                     float* __restrict__ q, float* __restrict__ k,
                     float* __restrict__ asp) {
    int blk = blockIdx.x;
    int tid = threadIdx.x;

    if (blk < 256) {
        // ---------- GEMM: C = g @ W + b, M=8192 N=100 K=100, BK=20 ----------
        __shared__ __align__(16) float As[2][20][68];
        __shared__ __align__(16) float Bs[2][20][104];

        const float* Bw; const float* bias; float* C;
        if (blk < 128) { Bw = q_w; bias = q_b; C = q; }
        else           { Bw = k_w; bias = k_b; C = k; }
        int m0 = (blk & 127) * 64;

        int tx = tid % 20, ty = tid / 20;
        int tx5 = tx * 5, ty4 = ty * 4;

        int ar = tid / 5, ac = (tid % 5) * 4;      // 320 threads = 64x20/4 exactly
        int b0r = tid / 25, b0c = (tid % 25) * 4;  // B tile 20x100 = 500 f4
        int bi1 = tid + 320;
        bool b1ok = (bi1 < 500);
        int b1r = bi1 / 25, b1c = (bi1 % 25) * 4;

        const float* Arow = g + (long long)(m0 + ar) * ATT;

        float acc[4][5];
        #pragma unroll
        for (int i = 0; i < 4; i++)
            #pragma unroll
            for (int j = 0; j < 5; j++) acc[i][j] = 0.f;

        float4 aR, bR0, bR1 = make_float4(0.f,0.f,0.f,0.f);
        aR = *reinterpret_cast<const float4*>(Arow + ac);
        bR0 = *reinterpret_cast<const float4*>(Bw + (long long)b0r * ATT + b0c);
        if (b1ok) bR1 = *reinterpret_cast<const float4*>(Bw + (long long)b1r * ATT + b1c);

        int s = 0;
        for (int t = 0; t < 5; t++) {
            As[s][ac + 0][ar] = aR.x;
            As[s][ac + 1][ar] = aR.y;
            As[s][ac + 2][ar] = aR.z;
            As[s][ac + 3][ar] = aR.w;
            *reinterpret_cast<float4*>(&Bs[s][b0r][b0c]) = bR0;
            if (b1ok) *reinterpret_cast<float4*>(&Bs[s][b1r][b1c]) = bR1;
            __syncthreads();
            if (t + 1 < 5) {
                int k0 = (t + 1) * 20;
                aR = *reinterpret_cast<const float4*>(Arow + k0 + ac);
                bR0 = *reinterpret_cast<const float4*>(Bw + (long long)(k0 + b0r) * ATT + b0c);
                if (b1ok) bR1 = *reinterpret_cast<const float4*>(Bw + (long long)(k0 + b1r) * ATT + b1c);
            }
            #pragma unroll
            for (int kk = 0; kk < 20; kk++) {
                float4 a4 = *reinterpret_cast<const float4*>(&As[s][kk][ty4]);
                float b0 = Bs[s][kk][tx5 + 0];
                float b1 = Bs[s][kk][tx5 + 1];
                float b2 = Bs[s][kk][tx5 + 2];
                float b3 = Bs[s][kk][tx5 + 3];
                float b4 = Bs[s][kk][tx5 + 4];
                acc[0][0] += a4.x*b0; acc[0][1] += a4.x*b1; acc[0][2] += a4.x*b2; acc[0][3] += a4.x*b3; acc[0][4] += a4.x*b4;
                acc[1][0] += a4.y*b0; acc[1][1] += a4.y*b1; acc[1][2] += a4.y*b2; acc[1][3] += a4.y*b3; acc[1][4] += a4.y*b4;
                acc[2][0] += a4.z*b0; acc[2][1] += a4.z*b1; acc[2][2] += a4.z*b2; acc[2][3] += a4.z*b3; acc[2][4] += a4.z*b4;
                acc[3][0] += a4.w*b0; acc[3][1] += a4.w*b1; acc[3][2] += a4.w*b2; acc[3][3] += a4.w*b3; acc[3][4] += a4.w*b4;
            }
            s ^= 1;
            __syncthreads();
        }

        float wb[5];
        #pragma unroll
        for (int j = 0; j < 5; j++) wb[j] = bias[tx5 + j];
        #pragma unroll
        for (int i = 0; i < 4; i++) {
            float* crow = C + (long long)(m0 + ty4 + i) * ATT;
            #pragma unroll
            for (int j = 0; j < 5; j++) crow[tx5 + j] = acc[i][j] + wb[j];
        }
    } else {
        // ---------- aspect pooling + asp GEMV (branchless) ----------
        int b = blk - 256;
        int w = tid >> 5, lane = tid & 31;
        __shared__ float smask[Ln];
        __shared__ float part[8][104];
        __shared__ float sa[104];
        __shared__ float wred[8];

        if (tid < 256) smask[tid] = amask[b * Ln + tid];
        __syncthreads();

        if (w < 8) {
            float acc[4] = {0.f, 0.f, 0.f, 0.f};
            float wsum = 0.f;
            const float* gb_ = g + (long long)b * Ln * ATT;
            for (int i = w * 32; i < w * 32 + 32; i++) {
                float m = smask[i];
                wsum += m;
                const float* gr = gb_ + (long long)i * ATT;
                #pragma unroll
                for (int c4 = 0; c4 < 4; c4++) {
                    int c = lane + c4 * 32;
                    float gv = (c < ATT) ? gr[c] : 0.f;
                    acc[c4] += gv * m;
                }
            }
            #pragma unroll
            for (int c4 = 0; c4 < 4; c4++) {
                int c = lane + c4 * 32;
                if (c < ATT) part[w][c] = acc[c4];
            }
            if (lane == 0) wred[w] = wsum;
        }
        __syncthreads();
        if (tid < ATT) {
            float s = 0.f;
            #pragma unroll
            for (int ww = 0; ww < 8; ww++) s += part[ww][tid];
            sa[tid] = s;
        }
        if (tid == 0) {
            float s = 0.f;
            #pragma unroll
            for (int ww = 0; ww < 8; ww++) s += wred[ww];
            wred[0] = 1.f / s;
        }
        __syncthreads();
        float inv = wred[0];
        if (tid < DK) {
            float s = dense_b[tid];
            for (int c = 0; c < ATT; c++) s += sa[c] * inv * dense_w[c * DK + tid];
            asp[b * DK + tid] = s;
        }
    }
}

// =====================================================================
// 3. scores + aspsc + mask + softmax -> adj ; also inits out = clf_b
// =====================================================================
__global__ __launch_bounds__(256, 4)
void scores_kernel(const float* __restrict__ q,
                   const float* __restrict__ k,
                   const float* __restrict__ asp,
                   const float* __restrict__ bias_m,
                   const int*   __restrict__ src_mask,
                   const float* __restrict__ short_mask,
                   const float* __restrict__ clf_b,
                   float* __restrict__ adj,
                   float* __restrict__ out) {
    int it = blockIdx.x, h = blockIdx.y, b = blockIdx.z;
    __shared__ float kt[Ln][21];
    __shared__ float addv[Ln];
    __shared__ float qs[8][20];
    __shared__ float sasp[DK];
    __shared__ int   msk[Ln];
    int t = threadIdx.x, w = t >> 5, lane = t & 31;
    int i = it * 8 + w;

    if (it == 0 && h == 0 && t < 3) out[b * 3 + t] = clf_b[t];

    if (t < DK) sasp[t] = asp[b * DK + t];
    msk[t] = src_mask[b * Ln + t];
    {
        const float4* kr = reinterpret_cast<const float4*>(
            k + ((long long)b * Ln + t) * ATT + h * DK);
        #pragma unroll
        for (int f = 0; f < 5; f++) {
            float4 v = kr[f];
            kt[t][f * 4 + 0] = v.x;
            kt[t][f * 4 + 1] = v.y;
            kt[t][f * 4 + 2] = v.z;
            kt[t][f * 4 + 3] = v.w;
        }
    }
    if (t < 160) {
        int r = t / 20, d = t % 20;
        qs[r][d] = q[((long long)b * Ln + it * 8 + r) * ATT + h * DK + d];
    }
    __syncthreads();
    {
        float s = 0.f;
        #pragma unroll
        for (int d = 0; d < DK; d++) s += sasp[d] * kt[t][d];
        addv[t] = tanhf(s + bias_m[0]);
    }
    __syncthreads();

    const float* srow = short_mask + ((long long)b * Ln + i) * Ln;
    float sc[8] = {0.f,0.f,0.f,0.f,0.f,0.f,0.f,0.f};
    #pragma unroll
    for (int d = 0; d < DK; d++) {
        float qd = qs[w][d];
        #pragma unroll
        for (int jj = 0; jj < 8; jj++)
            sc[jj] += qd * kt[lane + jj * 32][d];
    }
    const float rsd = 0.22360679774997896f;
    float mx = -3.4e38f;
    #pragma unroll
    for (int jj = 0; jj < 8; jj++) {
        int j = lane + jj * 32;
        float v = sc[jj] * rsd + addv[j];
        if (msk[j] == 0) v = -1e9f;
        v += srow[j];
        sc[jj] = v;
        mx = fmaxf(mx, v);
    }
    #pragma unroll
    for (int o = 16; o > 0; o >>= 1) mx = fmaxf(mx, __shfl_xor_sync(0xffffffffu, mx, o));
    float sum = 0.f;
    #pragma unroll
    for (int jj = 0; jj < 8; jj++) { sc[jj] = expf(sc[jj] - mx); sum += sc[jj]; }
    #pragma unroll
    for (int o = 16; o > 0; o >>= 1) sum += __shfl_xor_sync(0xffffffffu, sum, o);
    float invs = 1.f / sum;
    float* arow = adj + (((long long)(b * Hh + h)) * Ln + i) * Ln;
    #pragma unroll
    for (int jj = 0; jj < 8; jj++) arow[lane + jj * 32] = sc[jj] * invs;
}

// =====================================================================
// 4. Fused GCN layer. mode 0: out=relu((mean_h adj @ g)@W+b), writes go + sg1/sg2
//    mode 1: edge-collapsed A', computes relu GEMM result, fuses masked pool +
//            classifier (atomicAdd into out). go2 never hits gmem.
// =====================================================================
__global__ __launch_bounds__(320, 2)
void gcn_layer_kernel(const float* __restrict__ adj,
                      const float* __restrict__ Bsrc,
                      const float* __restrict__ W_w,
                      const float* __restrict__ W_b,
                      const float* __restrict__ sg1,
                      const float* __restrict__ sg2,
                      const float* __restrict__ Wx_w,
                      const float* __restrict__ Wx_b,
                      const float* __restrict__ amask,
                      const float* __restrict__ clf_w,
                      float* __restrict__ outC,
                      float* __restrict__ sg1o,
                      float* __restrict__ sg2o,
                      float* __restrict__ out,
                      int mode) {
    __shared__ __align__(16) float As[2][16][68];
    __shared__ __align__(16) float Bs[2][16][104];
    __shared__ __align__(16) float AxS[64][101];
    __shared__ float smask[Ln];
    __shared__ float swn;

    int b = blockIdx.z;
    int m0 = blockIdx.x * 64;
    int tid = threadIdx.x;
    int tx = tid % 20, ty = tid / 20;
    int tx5 = tx * 5, ty4 = ty * 4;

    const float* adjb = adj + (long long)b * Hh * 65536;
    const float* Bb   = Bsrc + (long long)b * (Ln * ATT);

    float ws0 = 0.f, ws1 = 0.f, ws2 = 0.f, ws3 = 0.f, ws4 = 0.f, sbb = 0.f;
    if (mode == 1) {
        #pragma unroll
        for (int kk2 = 0; kk2 < 5; kk2++) {
            ws0 += Wx_w[0 * 5 + kk2];
            ws1 += Wx_w[1 * 5 + kk2];
            ws2 += Wx_w[2 * 5 + kk2];
            ws3 += Wx_w[3 * 5 + kk2];
            ws4 += Wx_w[4 * 5 + kk2];
            sbb += Wx_b[kk2];
        }
        if (tid < 256) smask[tid] = amask[b * Ln + tid];
    }
    __syncthreads();
    if (mode == 1 && tid < 32) {
        float s = 0.f;
        #pragma unroll
        for (int i = 0; i < 8; i++) s += smask[tid * 8 + i];
        #pragma unroll
        for (int o = 16; o > 0; o >>= 1) s += __shfl_xor_sync(0xffffffffu, s, o);
        if (tid == 0) swn = 1.f / s;
    }

    int ar = tid >> 2, ac = (tid & 3) << 2;
    bool aok = (tid < 256);
    int b0r = tid / 25, b0c = (tid % 25) * 4;
    int bi1 = tid + 320;
    bool b1ok = (bi1 < 400);
    int b1r = bi1 / 25, b1c = (bi1 % 25) * 4;

    float acc[4][5];
    #pragma unroll
    for (int i = 0; i < 4; i++)
        #pragma unroll
        for (int j = 0; j < 5; j++) acc[i][j] = 0.f;

    float4 aR = make_float4(0.f,0.f,0.f,0.f);
    float4 bR0 = aR, bR1 = aR;

    #define LOAD_A(k0)                                                          \
        do {                                                                    \
            const float* basep = adjb + (long long)(m0 + ar) * 256 + ((k0) + ac); \
            float4 s_ = make_float4(0.f, 0.f, 0.f, 0.f);                        \
            if (mode == 0) {                                                    \
                _Pragma("unroll")                                               \
                for (int h_ = 0; h_ < 5; h_++) {                                \
                    float4 v_ = *reinterpret_cast<const float4*>(basep + h_ * 65536); \
                    s_.x += v_.x; s_.y += v_.y; s_.z += v_.z; s_.w += v_.w;     \
                }                                                               \
                s_.x *= 0.2f; s_.y *= 0.2f; s_.z *= 0.2f; s_.w *= 0.2f;         \
            } else {                                                            \
                float wsv_[5] = {ws0, ws1, ws2, ws3, ws4};                      \
                _Pragma("unroll")                                               \
                for (int h_ = 0; h_ < 5; h_++) {                                \
                    float4 v_ = *reinterpret_cast<const float4*>(basep + h_ * 65536); \
                    s_.x += v_.x * wsv_[h_]; s_.y += v_.y * wsv_[h_];           \
                    s_.z += v_.z * wsv_[h_]; s_.w += v_.w * wsv_[h_];           \
                }                                                               \
                float4 s1_ = *reinterpret_cast<const float4*>(sg1 + b * 256 + (k0) + ac); \
                float s2_ = sg2[b * 256 + m0 + ar];                             \
                float c_ = sbb + s2_;                                           \
                s_.x = 0.2f * (s_.x + c_ + s1_.x);                              \
                s_.y = 0.2f * (s_.y + c_ + s1_.y);                              \
                s_.z = 0.2f * (s_.z + c_ + s1_.z);                              \
                s_.w = 0.2f * (s_.w + c_ + s1_.w);                              \
            }                                                                   \
            aR = s_;                                                            \
        } while (0)

    if (aok) LOAD_A(0);
    bR0 = *reinterpret_cast<const float4*>(Bb + (long long)b0r * ATT + b0c);
    if (b1ok) bR1 = *reinterpret_cast<const float4*>(Bb + (long long)b1r * ATT + b1c);

    int s = 0;
    for (int t = 0; t < 16; t++) {
        if (aok) {
            As[s][ac + 0][ar] = aR.x;
            As[s][ac + 1][ar] = aR.y;
            As[s][ac + 2][ar] = aR.z;
            As[s][ac + 3][ar] = aR.w;
        }
        *reinterpret_cast<float4*>(&Bs[s][b0r][b0c]) = bR0;
        if (b1ok) *reinterpret_cast<float4*>(&Bs[s][b1r][b1c]) = bR1;
        __syncthreads();
        if (t + 1 < 16) {
            int k0 = (t + 1) * 16;
            if (aok) LOAD_A(k0);
            bR0 = *reinterpret_cast<const float4*>(Bb + (long long)(k0 + b0r) * ATT + b0c);
            if (b1ok) bR1 = *reinterpret_cast<const float4*>(Bb + (long long)(k0 + b1r) * ATT + b1c);
        }
        #pragma unroll
        for (int kk = 0; kk < 16; kk++) {
            float4 a4 = *reinterpret_cast<const float4*>(&As[s][kk][ty4]);
            float b0 = Bs[s][kk][tx5 + 0];
            float b1 = Bs[s][kk][tx5 + 1];
            float b2 = Bs[s][kk][tx5 + 2];
            float b3 = Bs[s][kk][tx5 + 3];
            float b4 = Bs[s][kk][tx5 + 4];
            acc[0][0] += a4.x*b0; acc[0][1] += a4.x*b1; acc[0][2] += a4.x*b2; acc[0][3] += a4.x*b3; acc[0][4] += a4.x*b4;
            acc[1][0] += a4.y*b0; acc[1][1] += a4.y*b1; acc[1][2] += a4.y*b2; acc[1][3] += a4.y*b3; acc[1][4] += a4.y*b4;
            acc[2][0] += a4.z*b0; acc[2][1] += a4.z*b1; acc[2][2] += a4.z*b2; acc[2][3] += a4.z*b3; acc[2][4] += a4.z*b4;
            acc[3][0] += a4.w*b0; acc[3][1] += a4.w*b1; acc[3][2] += a4.w*b2; acc[3][3] += a4.w*b3; acc[3][4] += a4.w*b4;
        }
        s ^= 1;
        __syncthreads();
    }
    #undef LOAD_A

    // stash Ax tile
    #pragma unroll
    for (int i = 0; i < 4; i++)
        #pragma unroll
        for (int j = 0; j < 5; j++)
            AxS[ty4 + i][tx5 + j] = acc[i][j];

    // second GEMM: acc2 = AxS @ W_w (K=100)
    float acc2[4][5];
    #pragma unroll
    for (int i = 0; i < 4; i++)
        #pragma unroll
        for (int j = 0; j < 5; j++) acc2[i][j] = 0.f;

    for (int k2 = 0; k2 < ATT; k2 += 16) {
        int kmax = ATT - k2; if (kmax > 16) kmax = 16;
        __syncthreads();
        for (int i = tid; i < 400; i += 320) {
            int row = i / 25, c4 = (i % 25) * 4;
            float4 v = make_float4(0.f,0.f,0.f,0.f);
            if (row < kmax) v = *reinterpret_cast<const float4*>(W_w + (long long)(k2 + row) * ATT + c4);
            *reinterpret_cast<float4*>(&Bs[0][row][c4]) = v;
        }
        __syncthreads();
        for (int kk = 0; kk < kmax; kk++) {
            float a0 = AxS[ty4 + 0][k2 + kk];
            float a1 = AxS[ty4 + 1][k2 + kk];
            float a2 = AxS[ty4 + 2][k2 + kk];
            float a3 = AxS[ty4 + 3][k2 + kk];
            float b0 = Bs[0][kk][tx5 + 0];
            float b1 = Bs[0][kk][tx5 + 1];
            float b2 = Bs[0][kk][tx5 + 2];
            float b3 = Bs[0][kk][tx5 + 3];
            float b4 = Bs[0][kk][tx5 + 4];
            acc2[0][0] += a0*b0; acc2[0][1] += a0*b1; acc2[0][2] += a0*b2; acc2[0][3] += a0*b3; acc2[0][4] += a0*b4;
            acc2[1][0] += a1*b0; acc2[1][1] += a1*b1; acc2[1][2] += a1*b2; acc2[1][3] += a1*b3; acc2[1][4] += a1*b4;
            acc2[2][0] += a2*b0; acc2[2][1] += a2*b1; acc2[2][2] += a2*b2; acc2[2][3] += a2*b3; acc2[2][4] += a2*b4;
            acc2[3][0] += a3*b0; acc2[3][1] += a3*b1; acc2[3][2] += a3*b2; acc2[3][3] += a3*b3; acc2[3][4] += a3*b4;
        }
    }

    float wb[5];
    #pragma unroll
    for (int j = 0; j < 5; j++) wb[j] = W_b[tx5 + j];

    if (mode == 0) {
        // w1s/w2s column sums computed in-thread (cheap broadcast loads)
        float w1r[5], w2r[5];
        #pragma unroll
        for (int j = 0; j < 5; j++) {
            float s1 = 0.f, s2 = 0.f;
            #pragma unroll
            for (int kk2 = 0; kk2 < 5; kk2++) {
                s1 += Wx_w[(5 + tx5 + j) * 5 + kk2];
                s2 += Wx_w[(105 + tx5 + j) * 5 + kk2];
            }
            w1r[j] = s1; w2r[j] = s2;
        }
        float p1[4] = {0.f,0.f,0.f,0.f}, p2[4] = {0.f,0.f,0.f,0.f};
        #pragma unroll
        for (int i = 0; i < 4; i++) {
            int gm = m0 + ty4 + i;
            float* crow = outC + ((long long)b * Ln + gm) * ATT;
            #pragma unroll
            for (int j = 0; j < 5; j++) {
                float v = fmaxf(acc2[i][j] + wb[j], 0.f);
                crow[tx5 + j] = v;
                p1[i] += v * w1r[j];
                p2[i] += v * w2r[j];
            }
        }
        __syncthreads();
        #pragma unroll
        for (int i = 0; i < 4; i++) {
            AxS[ty4 + i][tx]      = p1[i];
            AxS[ty4 + i][20 + tx] = p2[i];
        }
        __syncthreads();
        if (tid < 64) {
            float s1 = 0.f, s2 = 0.f;
            #pragma unroll
            for (int xx = 0; xx < 20; xx++) { s1 += AxS[tid][xx]; s2 += AxS[tid][20 + xx]; }
            sg1o[b * 256 + m0 + tid] = s1;
            sg2o[b * 256 + m0 + tid] = s2;
        }
    } else {
        // fused masked pool + classifier (no gmem write of go2)
        float pv[5] = {0.f,0.f,0.f,0.f,0.f};
        #pragma unroll
        for (int i = 0; i < 4; i++) {
            float m = smask[m0 + ty4 + i];
            #pragma unroll
            for (int j = 0; j < 5; j++)
                pv[j] += fmaxf(acc2[i][j] + wb[j], 0.f) * m;
        }
        __syncthreads();
        #pragma unroll
        for (int j = 0; j < 5; j++) AxS[ty][tx5 + j] = pv[j];
        __syncthreads();
        if (tid < ATT) {
            float s2 = 0.f;
            #pragma unroll
            for (int r = 0; r < 16; r++) s2 += AxS[r][tid];
            AxS[63][tid] = s2;
        }
        __syncthreads();
        if (tid < 3) {
            float s2 = 0.f;
            for (int c = 0; c < ATT; c++) s2 += AxS[63][c] * clf_w[c * 3 + tid];
            atomicAdd(out + b * 3 + tid, s2 * swn);
        }
    }
}

// ---------------- launch --------------------------------------------------
extern "C" void kernel_launch(void* const* d_in, const int* in_sizes, int n_in,
                              void* d_out, int out_size) {
    const float* seq     = (const float*)d_in[0];
    const int*   srcm    = (const int*)  d_in[1];
    const float* amask   = (const float*)d_in[2];
    const float* shortm  = (const float*)d_in[3];
    const float* ln_a    = (const float*)d_in[4];
    const float* ln_b    = (const float*)d_in[5];
    const float* Wxx_w   = (const float*)d_in[6];
    const float* Wxx_b   = (const float*)d_in[7];
    const float* q_w     = (const float*)d_in[8];
    const float* q_b     = (const float*)d_in[9];
    const float* k_w     = (const float*)d_in[10];
    const float* k_b     = (const float*)d_in[11];
    const float* dense_w = (const float*)d_in[12];
    const float* dense_b = (const float*)d_in[13];
    const float* bias_m  = (const float*)d_in[14];
    const float* W_w     = (const float*)d_in[15];
    const float* W_b     = (const float*)d_in[16];
    const float* Wx_w    = (const float*)d_in[17];
    const float* Wx_b    = (const float*)d_in[18];
    const float* clf_w   = (const float*)d_in[19];
    const float* clf_b   = (const float*)d_in[20];
    float* out = (float*)d_out;

    float* S = nullptr;
    cudaGetSymbolAddress((void**)&S, d_scratch);
    float* g     = S + OFF_G;
    float* q     = S + OFF_Q;
    float* k     = S + OFF_K;
    float* go    = S + OFF_GO;
    float* adj   = S + OFF_ADJ;
    float* asp   = S + OFF_ASP;
    float* sg1   = S + OFF_SG1;
    float* sg2   = S + OFF_SG2;

    // 1. fused layernorm + g GEMM
    lng_kernel<<<NROW / 64, 320>>>(seq, ln_a, ln_b, Wxx_w, Wxx_b, g);
    // 2. q/k projections + aspect pooling (one launch)
    qkaspect_kernel<<<288, 320>>>(g, q_w, q_b, k_w, k_b,
                                  amask, dense_w, dense_b, q, k, asp);
    // 3. scores + softmax -> adj (also inits out = clf_b)
    scores_kernel<<<dim3(Ln / 8, Hh, Bn), 256>>>(q, k, asp, bias_m, srcm, shortm,
                                                 clf_b, adj, out);
    // 4. GCN layer 0 (writes go, sg1, sg2)
    gcn_layer_kernel<<<dim3(Ln / 64, 1, Bn), 320>>>(adj, g, W_w, W_b,
                                                    nullptr, nullptr, Wx_w, Wx_b,
                                                    amask, clf_w,
                                                    go, sg1, sg2, out, 0);
    // 5. GCN layer 1 + fused final classifier (atomicAdd into out)
    gcn_layer_kernel<<<dim3(Ln / 64, 1, Bn), 320>>>(adj, go, W_w, W_b,
                                                    sg1, sg2, Wx_w, Wx_b,
                                                    amask, clf_w,
                                                    go, nullptr, nullptr, out, 1);
}